// round 2
// baseline (speedup 1.0000x reference)
#include <cuda_runtime.h>
#include <cstdint>

#define NTX_MAX 100000
#define NM_MAX  20000
#define E_MAX   500000

// ---------------- scratch (static device globals; no runtime allocation) ----------------
__device__ float g_proj_tx[(size_t)NTX_MAX * 192];  // [Q | Khat | Vhat]
__device__ float g_proj_m [(size_t)NM_MAX  * 192];
__device__ float g_agg_tx [(size_t)NTX_MAX * 64];
__device__ float g_agg_m  [(size_t)NM_MAX  * 64];
__device__ float g_h_tx   [(size_t)NTX_MAX * 64];
__device__ float g_h_m    [(size_t)NM_MAX  * 64];
__device__ float g_WA[128 * 192];   // effective fused QKV weights, type tx
__device__ float g_bA[192];
__device__ float g_WB[128 * 192];   // type m
__device__ float g_bB[192];
__device__ int g_rowptr0[NM_MAX + 1];   // dst = m   (tx->m edges)
__device__ int g_rowptr1[NTX_MAX + 1];  // dst = tx  (m->tx edges)
__device__ int g_cursor0[NM_MAX];
__device__ int g_cursor1[NTX_MAX];
__device__ int g_srcs0[E_MAX];
__device__ int g_srcs1[E_MAX];

// ---------------- CSR build ----------------
__global__ void zero_int_kernel(int* p, int n) {
    int i = blockIdx.x * blockDim.x + threadIdx.x;
    if (i < n) p[i] = 0;
}

__global__ void hist_kernel(const int* __restrict__ dst, int* __restrict__ cnt, int E) {
    int e = blockIdx.x * blockDim.x + threadIdx.x;
    if (e < E) atomicAdd(&cnt[dst[e]], 1);
}

// Single-block exclusive scan; writes rowptr[0..n] and cursor[i]=rowptr[i].
// cnt may alias cursor (each element read before written).
__global__ void scan_kernel(const int* __restrict__ cnt, int* __restrict__ rowptr,
                            int* __restrict__ cursor, int n) {
    __shared__ int ssum[1024];
    int tid = threadIdx.x;
    int chunk = (n + 1023) / 1024;
    int start = tid * chunk;
    int end = start + chunk; if (end > n) end = n; if (start > n) start = n;
    int s = 0;
    for (int i = start; i < end; i++) s += cnt[i];
    ssum[tid] = s;
    __syncthreads();
    for (int off = 1; off < 1024; off <<= 1) {
        int v = (tid >= off) ? ssum[tid - off] : 0;
        __syncthreads();
        ssum[tid] += v;
        __syncthreads();
    }
    int run = (tid == 0) ? 0 : ssum[tid - 1];
    for (int i = start; i < end; i++) {
        int c = cnt[i];
        rowptr[i] = run;
        cursor[i] = run;
        run += c;
    }
    if (tid == 1023) rowptr[n] = run;
}

__global__ void scatter_kernel(const int* __restrict__ src, const int* __restrict__ dst,
                               int* __restrict__ cursor, int* __restrict__ srcs_out, int E) {
    int e = blockIdx.x * blockDim.x + threadIdx.x;
    if (e < E) {
        int p = atomicAdd(&cursor[dst[e]], 1);
        srcs_out[p] = src[e];
    }
}

// ---------------- effective fused weights ----------------
// Wout[i*192 + c], c in [0,64): Q; [64,128): Wk (x) a_rel; [128,192): Wv (x) m_rel.
// Row i==din encodes the bias.
__global__ void eff_weights_kernel(const float* __restrict__ Wq, const float* __restrict__ bq,
                                   const float* __restrict__ Wk, const float* __restrict__ bk,
                                   const float* __restrict__ Wv, const float* __restrict__ bv,
                                   const float* __restrict__ a_rel, const float* __restrict__ m_rel,
                                   float* __restrict__ Wout, float* __restrict__ bout, int din) {
    int idx = blockIdx.x * blockDim.x + threadIdx.x;
    int total = (din + 1) * 192;
    if (idx >= total) return;
    int i = idx / 192, c = idx % 192;
    bool isBias = (i == din);
    float val;
    if (c < 64) {
        val = isBias ? bq[c] : Wq[i * 64 + c];
    } else {
        int cc = c - 64;
        bool isV = (cc >= 64);
        if (isV) cc -= 64;
        int h = cc >> 4, e = cc & 15;
        const float* rel  = isV ? m_rel : a_rel;
        const float* Wsrc = isV ? Wv : Wk;
        const float* bsrc = isV ? bv : bk;
        float s = 0.f;
        #pragma unroll
        for (int d = 0; d < 16; d++) {
            float w = isBias ? bsrc[h * 16 + d] : Wsrc[i * 64 + h * 16 + d];
            s += w * rel[h * 256 + d * 16 + e];
        }
        val = s;
    }
    if (isBias) bout[c] = val;
    else        Wout[i * 192 + c] = val;
}

// ---------------- fused QKV GEMM:  out[N,192] = X[N,DIN] @ W[DIN,192] + b ----------------
// 64-row x 64-col tile per block, 256 threads, 4x4 micro-tile, K-tiles of 64.
__global__ __launch_bounds__(256) void gemm_kernel(
    const float* __restrict__ X, int N, int DIN,
    const float* __restrict__ W, const float* __restrict__ bias,
    float* __restrict__ out, int col0) {
    __shared__ float xs[64 * 68];  // transposed [k][row], pad 68
    __shared__ float ws[64 * 64];  // [k][c]
    int row0 = blockIdx.x * 64;
    int cb = col0 + blockIdx.y * 64;
    int t = threadIdx.x;
    int tr = (t >> 4) * 4;
    int tc = (t & 15) * 4;
    float acc[4][4] = {};
    for (int k0 = 0; k0 < DIN; k0 += 64) {
        for (int i = t; i < 64 * 64; i += 256) {
            int kk = i & 63, r = i >> 6;
            int row = row0 + r;
            float v = (row < N) ? X[(size_t)row * DIN + k0 + kk] : 0.f;
            xs[kk * 68 + r] = v;
        }
        for (int i = t; i < 64 * 64; i += 256) {
            int c = i & 63, kk = i >> 6;
            ws[kk * 64 + c] = W[(k0 + kk) * 192 + cb + c];
        }
        __syncthreads();
        #pragma unroll 16
        for (int k = 0; k < 64; k++) {
            float4 xv = *(const float4*)(xs + k * 68 + tr);
            float4 wv = *(const float4*)(ws + k * 64 + tc);
            float xr[4] = {xv.x, xv.y, xv.z, xv.w};
            float wr[4] = {wv.x, wv.y, wv.z, wv.w};
            #pragma unroll
            for (int ii = 0; ii < 4; ii++)
                #pragma unroll
                for (int jj = 0; jj < 4; jj++)
                    acc[ii][jj] = fmaf(xr[ii], wr[jj], acc[ii][jj]);
        }
        __syncthreads();
    }
    #pragma unroll
    for (int ii = 0; ii < 4; ii++) {
        int row = row0 + tr + ii;
        if (row < N) {
            #pragma unroll
            for (int jj = 0; jj < 4; jj++)
                out[(size_t)row * 192 + cb + tc + jj] = acc[ii][jj] + bias[cb + tc + jj];
        }
    }
}

// ---------------- attention: warp per dst node, CSR over incoming edges ----------------
// lane owns channels ch=lane (heads 0/1) and ch=lane+32 (heads 2/3).
__global__ __launch_bounds__(256) void attn_kernel(
    const float* __restrict__ projS, const float* __restrict__ projD,
    const int* __restrict__ rowptr, const int* __restrict__ srcs,
    const float* __restrict__ p_rel, float* __restrict__ agg, int n_dst) {
    int w = threadIdx.x >> 5, lane = threadIdx.x & 31;
    int dst = blockIdx.x * 8 + w;
    if (dst >= n_dst) return;
    float q1 = projD[(size_t)dst * 192 + lane];
    float q2 = projD[(size_t)dst * 192 + 32 + lane];
    int hh = lane >> 4;                 // 0/1 within half-warp
    float p1 = p_rel[hh] * 0.25f;       // /SQRT_D fold
    float p2 = p_rel[2 + hh] * 0.25f;
    float acc1 = 0.f, acc2 = 0.f, den1 = 0.f, den2 = 0.f;
    int beg = rowptr[dst], end = rowptr[dst + 1];
    for (int i = beg; i < end; i++) {
        int s = srcs[i];
        const float* ps = projS + (size_t)s * 192;
        float k1 = ps[64 + lane];
        float k2 = ps[96 + lane];
        float v1 = ps[128 + lane];
        float v2 = ps[160 + lane];
        float t1 = q1 * k1, t2 = q2 * k2;
        #pragma unroll
        for (int off = 8; off; off >>= 1) {
            t1 += __shfl_xor_sync(0xffffffffu, t1, off);
            t2 += __shfl_xor_sync(0xffffffffu, t2, off);
        }
        float e1 = __expf(t1 * p1);
        float e2 = __expf(t2 * p2);
        acc1 = fmaf(e1, v1, acc1); den1 += e1;
        acc2 = fmaf(e2, v2, acc2); den2 += e2;
    }
    agg[(size_t)dst * 64 + lane]      = acc1 / (den1 + 1e-16f);
    agg[(size_t)dst * 64 + 32 + lane] = acc2 / (den2 + 1e-16f);
}

// ---------------- epilogue:  out = post( gelu(agg) @ Wa + ba ) ----------------
// MODE 0: relu (layer 1).  MODE 1: skip mix  out = a*o + (1-a)*x_in, a=sigmoid(skip[0]).
template <int MODE>
__global__ __launch_bounds__(256) void epilogue_kernel(
    const float* __restrict__ agg, const float* __restrict__ Wa, const float* __restrict__ ba,
    const float* __restrict__ x_in, const float* __restrict__ skipv,
    float* __restrict__ out, int N) {
    __shared__ float gs[64 * 68];  // transposed gelu(agg) [k][row]
    __shared__ float ws[64 * 64];  // Wa [k][j]
    int row0 = blockIdx.x * 64;
    int t = threadIdx.x;
    for (int i = t; i < 64 * 64; i += 256) {
        int kk = i & 63, r = i >> 6;
        int row = row0 + r;
        float v = (row < N) ? agg[(size_t)row * 64 + kk] : 0.f;
        v = 0.5f * v * (1.f + erff(v * 0.70710678118654752f));
        gs[kk * 68 + r] = v;
        ws[i] = Wa[i];
    }
    __syncthreads();
    int tr = (t >> 4) * 4;
    int tc = (t & 15) * 4;
    float acc[4][4] = {};
    #pragma unroll 16
    for (int k = 0; k < 64; k++) {
        float4 xv = *(const float4*)(gs + k * 68 + tr);
        float4 wv = *(const float4*)(ws + k * 64 + tc);
        float xr[4] = {xv.x, xv.y, xv.z, xv.w};
        float wr[4] = {wv.x, wv.y, wv.z, wv.w};
        #pragma unroll
        for (int ii = 0; ii < 4; ii++)
            #pragma unroll
            for (int jj = 0; jj < 4; jj++)
                acc[ii][jj] = fmaf(xr[ii], wr[jj], acc[ii][jj]);
    }
    float a = 0.f;
    if (MODE == 1) a = 1.f / (1.f + __expf(-skipv[0]));
    #pragma unroll
    for (int ii = 0; ii < 4; ii++) {
        int row = row0 + tr + ii;
        if (row < N) {
            #pragma unroll
            for (int jj = 0; jj < 4; jj++) {
                float o = acc[ii][jj] + ba[tc + jj];
                if (MODE == 0) o = fmaxf(o, 0.f);
                else           o = a * o + (1.f - a) * x_in[(size_t)row * 64 + tc + jj];
                out[(size_t)row * 64 + tc + jj] = o;
            }
        }
    }
}

// ---------------- final logits:  out[n] = h[n,:] . Wc + bc ----------------
__global__ __launch_bounds__(256) void final_kernel(
    const float* __restrict__ h, const float* __restrict__ Wc, const float* __restrict__ bc,
    float* __restrict__ out, int N) {
    int warp = (blockIdx.x * blockDim.x + threadIdx.x) >> 5;
    int lane = threadIdx.x & 31;
    if (warp >= N) return;
    float s = h[(size_t)warp * 64 + lane] * Wc[lane] + h[(size_t)warp * 64 + 32 + lane] * Wc[32 + lane];
    #pragma unroll
    for (int off = 16; off; off >>= 1) s += __shfl_xor_sync(0xffffffffu, s, off);
    if (lane == 0) out[warp] = s + bc[0];
}

// ---------------- launch ----------------
extern "C" void kernel_launch(void* const* d_in, const int* in_sizes, int n_in,
                              void* d_out, int out_size) {
    (void)n_in; (void)out_size;
    // Detect input ordering: dict order (edges at 2..5) vs signature order (edges at 27..30)
    int ebase, wbase;
    if (in_sizes[2] > 100000) { ebase = 2;  wbase = 6; }
    else                      { ebase = 27; wbase = 2; }

    const float* x_tx = (const float*)d_in[0];
    const float* x_m  = (const float*)d_in[1];
    const int* tm_src = (const int*)d_in[ebase + 0];
    const int* tm_dst = (const int*)d_in[ebase + 1];
    const int* mt_src = (const int*)d_in[ebase + 2];
    const int* mt_dst = (const int*)d_in[ebase + 3];

    const float* c1_Wk    = (const float*)d_in[wbase + 0];
    const float* c1_bk    = (const float*)d_in[wbase + 1];
    const float* c1_Wq    = (const float*)d_in[wbase + 2];
    const float* c1_bq    = (const float*)d_in[wbase + 3];
    const float* c1_Wv    = (const float*)d_in[wbase + 4];
    const float* c1_bv    = (const float*)d_in[wbase + 5];
    const float* c1_a_rel = (const float*)d_in[wbase + 6];
    const float* c1_m_rel = (const float*)d_in[wbase + 7];
    const float* c1_p_rel = (const float*)d_in[wbase + 8];
    const float* c1_Wa    = (const float*)d_in[wbase + 9];
    const float* c1_ba    = (const float*)d_in[wbase + 10];
    const float* c2_Wk    = (const float*)d_in[wbase + 11];
    const float* c2_bk    = (const float*)d_in[wbase + 12];
    const float* c2_Wq    = (const float*)d_in[wbase + 13];
    const float* c2_bq    = (const float*)d_in[wbase + 14];
    const float* c2_Wv    = (const float*)d_in[wbase + 15];
    const float* c2_bv    = (const float*)d_in[wbase + 16];
    const float* c2_a_rel = (const float*)d_in[wbase + 17];
    const float* c2_m_rel = (const float*)d_in[wbase + 18];
    const float* c2_p_rel = (const float*)d_in[wbase + 19];
    const float* c2_Wa    = (const float*)d_in[wbase + 20];
    const float* c2_ba    = (const float*)d_in[wbase + 21];
    const float* c2_skip  = (const float*)d_in[wbase + 22];
    const float* Wc       = (const float*)d_in[wbase + 23];
    const float* bc       = (const float*)d_in[wbase + 24];

    int N_TX = in_sizes[0] / 128;
    int N_M  = in_sizes[1] / 128;
    int E0 = in_sizes[ebase + 1];
    int E1 = in_sizes[ebase + 3];

    // symbol addresses
    void* p;
    float *proj_tx, *proj_m, *agg_tx, *agg_m, *h_tx, *h_m, *WA, *bA, *WB, *bB;
    int *rowptr0, *rowptr1, *cursor0, *cursor1, *srcs0, *srcs1;
    cudaGetSymbolAddress(&p, g_proj_tx); proj_tx = (float*)p;
    cudaGetSymbolAddress(&p, g_proj_m);  proj_m  = (float*)p;
    cudaGetSymbolAddress(&p, g_agg_tx);  agg_tx  = (float*)p;
    cudaGetSymbolAddress(&p, g_agg_m);   agg_m   = (float*)p;
    cudaGetSymbolAddress(&p, g_h_tx);    h_tx    = (float*)p;
    cudaGetSymbolAddress(&p, g_h_m);     h_m     = (float*)p;
    cudaGetSymbolAddress(&p, g_WA);      WA      = (float*)p;
    cudaGetSymbolAddress(&p, g_bA);      bA      = (float*)p;
    cudaGetSymbolAddress(&p, g_WB);      WB      = (float*)p;
    cudaGetSymbolAddress(&p, g_bB);      bB      = (float*)p;
    cudaGetSymbolAddress(&p, g_rowptr0); rowptr0 = (int*)p;
    cudaGetSymbolAddress(&p, g_rowptr1); rowptr1 = (int*)p;
    cudaGetSymbolAddress(&p, g_cursor0); cursor0 = (int*)p;
    cudaGetSymbolAddress(&p, g_cursor1); cursor1 = (int*)p;
    cudaGetSymbolAddress(&p, g_srcs0);   srcs0   = (int*)p;
    cudaGetSymbolAddress(&p, g_srcs1);   srcs1   = (int*)p;

    // ---- CSR build (per launch; edge indices are inputs) ----
    zero_int_kernel<<<(N_M + 255) / 256, 256>>>(cursor0, N_M);
    zero_int_kernel<<<(N_TX + 255) / 256, 256>>>(cursor1, N_TX);
    hist_kernel<<<(E0 + 255) / 256, 256>>>(tm_dst, cursor0, E0);
    hist_kernel<<<(E1 + 255) / 256, 256>>>(mt_dst, cursor1, E1);
    scan_kernel<<<1, 1024>>>(cursor0, rowptr0, cursor0, N_M);
    scan_kernel<<<1, 1024>>>(cursor1, rowptr1, cursor1, N_TX);
    scatter_kernel<<<(E0 + 255) / 256, 256>>>(tm_src, tm_dst, cursor0, srcs0, E0);
    scatter_kernel<<<(E1 + 255) / 256, 256>>>(mt_src, mt_dst, cursor1, srcs1, E1);

    // ---- layer 1 (din = 128) ----
    {
        int din = 128;
        int effN = (din + 1) * 192;
        eff_weights_kernel<<<(effN + 255) / 256, 256>>>(
            c1_Wq, c1_bq, c1_Wk, c1_bk, c1_Wv, c1_bv, c1_a_rel, c1_m_rel, WA, bA, din);
        eff_weights_kernel<<<(effN + 255) / 256, 256>>>(
            c1_Wq + din * 64, c1_bq + 64, c1_Wk + din * 64, c1_bk + 64,
            c1_Wv + din * 64, c1_bv + 64, c1_a_rel + 1024, c1_m_rel + 1024, WB, bB, din);
        gemm_kernel<<<dim3((N_TX + 63) / 64, 3), 256>>>(x_tx, N_TX, din, WA, bA, proj_tx, 0);
        gemm_kernel<<<dim3((N_M + 63) / 64, 3), 256>>>(x_m, N_M, din, WB, bB, proj_m, 0);
        attn_kernel<<<(N_M + 7) / 8, 256>>>(proj_tx, proj_m, rowptr0, srcs0, c1_p_rel, agg_m, N_M);
        attn_kernel<<<(N_TX + 7) / 8, 256>>>(proj_m, proj_tx, rowptr1, srcs1, c1_p_rel + 4, agg_tx, N_TX);
        epilogue_kernel<0><<<(N_TX + 63) / 64, 256>>>(agg_tx, c1_Wa, c1_ba, nullptr, nullptr, h_tx, N_TX);
        epilogue_kernel<0><<<(N_M + 63) / 64, 256>>>(agg_m, c1_Wa + 4096, c1_ba + 64, nullptr, nullptr, h_m, N_M);
    }

    // ---- layer 2 (din = 64); only the tx destination path feeds the output ----
    {
        int din = 64;
        int effN = (din + 1) * 192;
        eff_weights_kernel<<<(effN + 255) / 256, 256>>>(
            c2_Wq, c2_bq, c2_Wk, c2_bk, c2_Wv, c2_bv, c2_a_rel, c2_m_rel, WA, bA, din);
        eff_weights_kernel<<<(effN + 255) / 256, 256>>>(
            c2_Wq + din * 64, c2_bq + 64, c2_Wk + din * 64, c2_bk + 64,
            c2_Wv + din * 64, c2_bv + 64, c2_a_rel + 1024, c2_m_rel + 1024, WB, bB, din);
        // tx needs only Q (cols 0..63); m needs only Khat/Vhat (cols 64..191)
        gemm_kernel<<<dim3((N_TX + 63) / 64, 1), 256>>>(h_tx, N_TX, din, WA, bA, proj_tx, 0);
        gemm_kernel<<<dim3((N_M + 63) / 64, 2), 256>>>(h_m, N_M, din, WB, bB, proj_m, 64);
        attn_kernel<<<(N_TX + 7) / 8, 256>>>(proj_m, proj_tx, rowptr1, srcs1, c2_p_rel + 4, agg_tx, N_TX);
        // skip-mix epilogue, in place on h_tx (each element read+written by the same thread)
        epilogue_kernel<1><<<(N_TX + 63) / 64, 256>>>(agg_tx, c2_Wa, c2_ba, h_tx, c2_skip, h_tx, N_TX);
    }

    final_kernel<<<(N_TX + 7) / 8, 256>>>(h_tx, Wc, bc, (float*)d_out, N_TX);
}

// round 3
// speedup vs baseline: 1.0000x; 1.0000x over previous
#include <cuda_runtime.h>
#include <cstdint>

#define NTX_MAX 100000
#define NM_MAX  20000
#define E_MAX   500000

// ---------------- scratch (static device globals; no runtime allocation) ----------------
__device__ float g_proj_tx[(size_t)NTX_MAX * 192];  // [Q | Khat | Vhat]
__device__ float g_proj_m [(size_t)NM_MAX  * 192];
__device__ float g_agg_tx [(size_t)NTX_MAX * 64];
__device__ float g_agg_m  [(size_t)NM_MAX  * 64];
__device__ float g_h_tx   [(size_t)NTX_MAX * 64];
__device__ float g_h_m    [(size_t)NM_MAX  * 64];
__device__ float g_WA[128 * 192];   // effective fused QKV weights, type tx
__device__ float g_bA[192];
__device__ float g_WB[128 * 192];   // type m
__device__ float g_bB[192];
__device__ int g_rowptr0[NM_MAX + 1];   // dst = m   (tx->m edges)
__device__ int g_rowptr1[NTX_MAX + 1];  // dst = tx  (m->tx edges)
__device__ int g_cursor0[NM_MAX];
__device__ int g_cursor1[NTX_MAX];
__device__ int g_srcs0[E_MAX];
__device__ int g_srcs1[E_MAX];

// ---------------- CSR build ----------------
__global__ void zero_int_kernel(int* p, int n) {
    int i = blockIdx.x * blockDim.x + threadIdx.x;
    if (i < n) p[i] = 0;
}

__global__ void hist_kernel(const int* __restrict__ dst, int* __restrict__ cnt, int E) {
    int e = blockIdx.x * blockDim.x + threadIdx.x;
    if (e < E) atomicAdd(&cnt[dst[e]], 1);
}

// Single-block exclusive scan; writes rowptr[0..n] and cursor[i]=rowptr[i].
// cnt may alias cursor (each element read before written).
__global__ void scan_kernel(const int* __restrict__ cnt, int* __restrict__ rowptr,
                            int* __restrict__ cursor, int n) {
    __shared__ int ssum[1024];
    int tid = threadIdx.x;
    int chunk = (n + 1023) / 1024;
    int start = tid * chunk;
    int end = start + chunk; if (end > n) end = n; if (start > n) start = n;
    int s = 0;
    for (int i = start; i < end; i++) s += cnt[i];
    ssum[tid] = s;
    __syncthreads();
    for (int off = 1; off < 1024; off <<= 1) {
        int v = (tid >= off) ? ssum[tid - off] : 0;
        __syncthreads();
        ssum[tid] += v;
        __syncthreads();
    }
    int run = (tid == 0) ? 0 : ssum[tid - 1];
    for (int i = start; i < end; i++) {
        int c = cnt[i];
        rowptr[i] = run;
        cursor[i] = run;
        run += c;
    }
    if (tid == 1023) rowptr[n] = run;
}

__global__ void scatter_kernel(const int* __restrict__ src, const int* __restrict__ dst,
                               int* __restrict__ cursor, int* __restrict__ srcs_out, int E) {
    int e = blockIdx.x * blockDim.x + threadIdx.x;
    if (e < E) {
        int p = atomicAdd(&cursor[dst[e]], 1);
        srcs_out[p] = src[e];
    }
}

// ---------------- effective fused weights ----------------
// Wout[i*192 + c], c in [0,64): Q; [64,128): Wk (x) a_rel; [128,192): Wv (x) m_rel.
// Row i==din encodes the bias.
__global__ void eff_weights_kernel(const float* __restrict__ Wq, const float* __restrict__ bq,
                                   const float* __restrict__ Wk, const float* __restrict__ bk,
                                   const float* __restrict__ Wv, const float* __restrict__ bv,
                                   const float* __restrict__ a_rel, const float* __restrict__ m_rel,
                                   float* __restrict__ Wout, float* __restrict__ bout, int din) {
    int idx = blockIdx.x * blockDim.x + threadIdx.x;
    int total = (din + 1) * 192;
    if (idx >= total) return;
    int i = idx / 192, c = idx % 192;
    bool isBias = (i == din);
    float val;
    if (c < 64) {
        val = isBias ? bq[c] : Wq[i * 64 + c];
    } else {
        int cc = c - 64;
        bool isV = (cc >= 64);
        if (isV) cc -= 64;
        int h = cc >> 4, e = cc & 15;
        const float* rel  = isV ? m_rel : a_rel;
        const float* Wsrc = isV ? Wv : Wk;
        const float* bsrc = isV ? bv : bk;
        float s = 0.f;
        #pragma unroll
        for (int d = 0; d < 16; d++) {
            float w = isBias ? bsrc[h * 16 + d] : Wsrc[i * 64 + h * 16 + d];
            s += w * rel[h * 256 + d * 16 + e];
        }
        val = s;
    }
    if (isBias) bout[c] = val;
    else        Wout[i * 192 + c] = val;
}

// ---------------- fused QKV GEMM:  out[N,192] = X[N,DIN] @ W[DIN,192] + b ----------------
// 64-row x 64-col tile per block, 256 threads, 4x4 micro-tile, K-tiles of 64.
__global__ __launch_bounds__(256) void gemm_kernel(
    const float* __restrict__ X, int N, int DIN,
    const float* __restrict__ W, const float* __restrict__ bias,
    float* __restrict__ out, int col0) {
    __shared__ float xs[64 * 68];  // transposed [k][row], pad 68
    __shared__ float ws[64 * 64];  // [k][c]
    int row0 = blockIdx.x * 64;
    int cb = col0 + blockIdx.y * 64;
    int t = threadIdx.x;
    int tr = (t >> 4) * 4;
    int tc = (t & 15) * 4;
    float acc[4][4] = {};
    for (int k0 = 0; k0 < DIN; k0 += 64) {
        for (int i = t; i < 64 * 64; i += 256) {
            int kk = i & 63, r = i >> 6;
            int row = row0 + r;
            float v = (row < N) ? X[(size_t)row * DIN + k0 + kk] : 0.f;
            xs[kk * 68 + r] = v;
        }
        for (int i = t; i < 64 * 64; i += 256) {
            int c = i & 63, kk = i >> 6;
            ws[kk * 64 + c] = W[(k0 + kk) * 192 + cb + c];
        }
        __syncthreads();
        #pragma unroll 16
        for (int k = 0; k < 64; k++) {
            float4 xv = *(const float4*)(xs + k * 68 + tr);
            float4 wv = *(const float4*)(ws + k * 64 + tc);
            float xr[4] = {xv.x, xv.y, xv.z, xv.w};
            float wr[4] = {wv.x, wv.y, wv.z, wv.w};
            #pragma unroll
            for (int ii = 0; ii < 4; ii++)
                #pragma unroll
                for (int jj = 0; jj < 4; jj++)
                    acc[ii][jj] = fmaf(xr[ii], wr[jj], acc[ii][jj]);
        }
        __syncthreads();
    }
    #pragma unroll
    for (int ii = 0; ii < 4; ii++) {
        int row = row0 + tr + ii;
        if (row < N) {
            #pragma unroll
            for (int jj = 0; jj < 4; jj++)
                out[(size_t)row * 192 + cb + tc + jj] = acc[ii][jj] + bias[cb + tc + jj];
        }
    }
}

// ---------------- attention: warp per dst node, CSR over incoming edges ----------------
// lane owns channels ch=lane (heads 0/1) and ch=lane+32 (heads 2/3).
__global__ __launch_bounds__(256) void attn_kernel(
    const float* __restrict__ projS, const float* __restrict__ projD,
    const int* __restrict__ rowptr, const int* __restrict__ srcs,
    const float* __restrict__ p_rel, float* __restrict__ agg, int n_dst) {
    int w = threadIdx.x >> 5, lane = threadIdx.x & 31;
    int dst = blockIdx.x * 8 + w;
    if (dst >= n_dst) return;
    float q1 = projD[(size_t)dst * 192 + lane];
    float q2 = projD[(size_t)dst * 192 + 32 + lane];
    int hh = lane >> 4;                 // 0/1 within half-warp
    float p1 = p_rel[hh] * 0.25f;       // /SQRT_D fold
    float p2 = p_rel[2 + hh] * 0.25f;
    float acc1 = 0.f, acc2 = 0.f, den1 = 0.f, den2 = 0.f;
    int beg = rowptr[dst], end = rowptr[dst + 1];
    for (int i = beg; i < end; i++) {
        int s = srcs[i];
        const float* ps = projS + (size_t)s * 192;
        float k1 = ps[64 + lane];
        float k2 = ps[96 + lane];
        float v1 = ps[128 + lane];
        float v2 = ps[160 + lane];
        float t1 = q1 * k1, t2 = q2 * k2;
        #pragma unroll
        for (int off = 8; off; off >>= 1) {
            t1 += __shfl_xor_sync(0xffffffffu, t1, off);
            t2 += __shfl_xor_sync(0xffffffffu, t2, off);
        }
        float e1 = __expf(t1 * p1);
        float e2 = __expf(t2 * p2);
        acc1 = fmaf(e1, v1, acc1); den1 += e1;
        acc2 = fmaf(e2, v2, acc2); den2 += e2;
    }
    agg[(size_t)dst * 64 + lane]      = acc1 / (den1 + 1e-16f);
    agg[(size_t)dst * 64 + 32 + lane] = acc2 / (den2 + 1e-16f);
}

// ---------------- epilogue:  out = post( gelu(agg) @ Wa + ba ) ----------------
// MODE 0: relu (layer 1).  MODE 1: skip mix  out = a*o + (1-a)*x_in, a=sigmoid(skip[0]).
template <int MODE>
__global__ __launch_bounds__(256) void epilogue_kernel(
    const float* __restrict__ agg, const float* __restrict__ Wa, const float* __restrict__ ba,
    const float* __restrict__ x_in, const float* __restrict__ skipv,
    float* __restrict__ out, int N) {
    __shared__ float gs[64 * 68];  // transposed gelu(agg) [k][row]
    __shared__ float ws[64 * 64];  // Wa [k][j]
    int row0 = blockIdx.x * 64;
    int t = threadIdx.x;
    for (int i = t; i < 64 * 64; i += 256) {
        int kk = i & 63, r = i >> 6;
        int row = row0 + r;
        float v = (row < N) ? agg[(size_t)row * 64 + kk] : 0.f;
        v = 0.5f * v * (1.f + erff(v * 0.70710678118654752f));
        gs[kk * 68 + r] = v;
        ws[i] = Wa[i];
    }
    __syncthreads();
    int tr = (t >> 4) * 4;
    int tc = (t & 15) * 4;
    float acc[4][4] = {};
    #pragma unroll 16
    for (int k = 0; k < 64; k++) {
        float4 xv = *(const float4*)(gs + k * 68 + tr);
        float4 wv = *(const float4*)(ws + k * 64 + tc);
        float xr[4] = {xv.x, xv.y, xv.z, xv.w};
        float wr[4] = {wv.x, wv.y, wv.z, wv.w};
        #pragma unroll
        for (int ii = 0; ii < 4; ii++)
            #pragma unroll
            for (int jj = 0; jj < 4; jj++)
                acc[ii][jj] = fmaf(xr[ii], wr[jj], acc[ii][jj]);
    }
    float a = 0.f;
    if (MODE == 1) a = 1.f / (1.f + __expf(-skipv[0]));
    #pragma unroll
    for (int ii = 0; ii < 4; ii++) {
        int row = row0 + tr + ii;
        if (row < N) {
            #pragma unroll
            for (int jj = 0; jj < 4; jj++) {
                float o = acc[ii][jj] + ba[tc + jj];
                if (MODE == 0) o = fmaxf(o, 0.f);
                else           o = a * o + (1.f - a) * x_in[(size_t)row * 64 + tc + jj];
                out[(size_t)row * 64 + tc + jj] = o;
            }
        }
    }
}

// ---------------- final logits:  out[n] = h[n,:] . Wc + bc ----------------
__global__ __launch_bounds__(256) void final_kernel(
    const float* __restrict__ h, const float* __restrict__ Wc, const float* __restrict__ bc,
    float* __restrict__ out, int N) {
    int warp = (blockIdx.x * blockDim.x + threadIdx.x) >> 5;
    int lane = threadIdx.x & 31;
    if (warp >= N) return;
    float s = h[(size_t)warp * 64 + lane] * Wc[lane] + h[(size_t)warp * 64 + 32 + lane] * Wc[32 + lane];
    #pragma unroll
    for (int off = 16; off; off >>= 1) s += __shfl_xor_sync(0xffffffffu, s, off);
    if (lane == 0) out[warp] = s + bc[0];
}

// ---------------- launch ----------------
extern "C" void kernel_launch(void* const* d_in, const int* in_sizes, int n_in,
                              void* d_out, int out_size) {
    (void)n_in; (void)out_size;
    // Detect input ordering: dict order (edges at 2..5) vs signature order (edges at 27..30)
    int ebase, wbase;
    if (in_sizes[2] > 100000) { ebase = 2;  wbase = 6; }
    else                      { ebase = 27; wbase = 2; }

    const float* x_tx = (const float*)d_in[0];
    const float* x_m  = (const float*)d_in[1];
    const int* tm_src = (const int*)d_in[ebase + 0];
    const int* tm_dst = (const int*)d_in[ebase + 1];
    const int* mt_src = (const int*)d_in[ebase + 2];
    const int* mt_dst = (const int*)d_in[ebase + 3];

    const float* c1_Wk    = (const float*)d_in[wbase + 0];
    const float* c1_bk    = (const float*)d_in[wbase + 1];
    const float* c1_Wq    = (const float*)d_in[wbase + 2];
    const float* c1_bq    = (const float*)d_in[wbase + 3];
    const float* c1_Wv    = (const float*)d_in[wbase + 4];
    const float* c1_bv    = (const float*)d_in[wbase + 5];
    const float* c1_a_rel = (const float*)d_in[wbase + 6];
    const float* c1_m_rel = (const float*)d_in[wbase + 7];
    const float* c1_p_rel = (const float*)d_in[wbase + 8];
    const float* c1_Wa    = (const float*)d_in[wbase + 9];
    const float* c1_ba    = (const float*)d_in[wbase + 10];
    const float* c2_Wk    = (const float*)d_in[wbase + 11];
    const float* c2_bk    = (const float*)d_in[wbase + 12];
    const float* c2_Wq    = (const float*)d_in[wbase + 13];
    const float* c2_bq    = (const float*)d_in[wbase + 14];
    const float* c2_Wv    = (const float*)d_in[wbase + 15];
    const float* c2_bv    = (const float*)d_in[wbase + 16];
    const float* c2_a_rel = (const float*)d_in[wbase + 17];
    const float* c2_m_rel = (const float*)d_in[wbase + 18];
    const float* c2_p_rel = (const float*)d_in[wbase + 19];
    const float* c2_Wa    = (const float*)d_in[wbase + 20];
    const float* c2_ba    = (const float*)d_in[wbase + 21];
    const float* c2_skip  = (const float*)d_in[wbase + 22];
    const float* Wc       = (const float*)d_in[wbase + 23];
    const float* bc       = (const float*)d_in[wbase + 24];

    int N_TX = in_sizes[0] / 128;
    int N_M  = in_sizes[1] / 128;
    int E0 = in_sizes[ebase + 1];
    int E1 = in_sizes[ebase + 3];

    // symbol addresses
    void* p;
    float *proj_tx, *proj_m, *agg_tx, *agg_m, *h_tx, *h_m, *WA, *bA, *WB, *bB;
    int *rowptr0, *rowptr1, *cursor0, *cursor1, *srcs0, *srcs1;
    cudaGetSymbolAddress(&p, g_proj_tx); proj_tx = (float*)p;
    cudaGetSymbolAddress(&p, g_proj_m);  proj_m  = (float*)p;
    cudaGetSymbolAddress(&p, g_agg_tx);  agg_tx  = (float*)p;
    cudaGetSymbolAddress(&p, g_agg_m);   agg_m   = (float*)p;
    cudaGetSymbolAddress(&p, g_h_tx);    h_tx    = (float*)p;
    cudaGetSymbolAddress(&p, g_h_m);     h_m     = (float*)p;
    cudaGetSymbolAddress(&p, g_WA);      WA      = (float*)p;
    cudaGetSymbolAddress(&p, g_bA);      bA      = (float*)p;
    cudaGetSymbolAddress(&p, g_WB);      WB      = (float*)p;
    cudaGetSymbolAddress(&p, g_bB);      bB      = (float*)p;
    cudaGetSymbolAddress(&p, g_rowptr0); rowptr0 = (int*)p;
    cudaGetSymbolAddress(&p, g_rowptr1); rowptr1 = (int*)p;
    cudaGetSymbolAddress(&p, g_cursor0); cursor0 = (int*)p;
    cudaGetSymbolAddress(&p, g_cursor1); cursor1 = (int*)p;
    cudaGetSymbolAddress(&p, g_srcs0);   srcs0   = (int*)p;
    cudaGetSymbolAddress(&p, g_srcs1);   srcs1   = (int*)p;

    // ---- CSR build (per launch; edge indices are inputs) ----
    zero_int_kernel<<<(N_M + 255) / 256, 256>>>(cursor0, N_M);
    zero_int_kernel<<<(N_TX + 255) / 256, 256>>>(cursor1, N_TX);
    hist_kernel<<<(E0 + 255) / 256, 256>>>(tm_dst, cursor0, E0);
    hist_kernel<<<(E1 + 255) / 256, 256>>>(mt_dst, cursor1, E1);
    scan_kernel<<<1, 1024>>>(cursor0, rowptr0, cursor0, N_M);
    scan_kernel<<<1, 1024>>>(cursor1, rowptr1, cursor1, N_TX);
    scatter_kernel<<<(E0 + 255) / 256, 256>>>(tm_src, tm_dst, cursor0, srcs0, E0);
    scatter_kernel<<<(E1 + 255) / 256, 256>>>(mt_src, mt_dst, cursor1, srcs1, E1);

    // ---- layer 1 (din = 128) ----
    {
        int din = 128;
        int effN = (din + 1) * 192;
        eff_weights_kernel<<<(effN + 255) / 256, 256>>>(
            c1_Wq, c1_bq, c1_Wk, c1_bk, c1_Wv, c1_bv, c1_a_rel, c1_m_rel, WA, bA, din);
        eff_weights_kernel<<<(effN + 255) / 256, 256>>>(
            c1_Wq + din * 64, c1_bq + 64, c1_Wk + din * 64, c1_bk + 64,
            c1_Wv + din * 64, c1_bv + 64, c1_a_rel + 1024, c1_m_rel + 1024, WB, bB, din);
        gemm_kernel<<<dim3((N_TX + 63) / 64, 3), 256>>>(x_tx, N_TX, din, WA, bA, proj_tx, 0);
        gemm_kernel<<<dim3((N_M + 63) / 64, 3), 256>>>(x_m, N_M, din, WB, bB, proj_m, 0);
        attn_kernel<<<(N_M + 7) / 8, 256>>>(proj_tx, proj_m, rowptr0, srcs0, c1_p_rel, agg_m, N_M);
        attn_kernel<<<(N_TX + 7) / 8, 256>>>(proj_m, proj_tx, rowptr1, srcs1, c1_p_rel + 4, agg_tx, N_TX);
        epilogue_kernel<0><<<(N_TX + 63) / 64, 256>>>(agg_tx, c1_Wa, c1_ba, nullptr, nullptr, h_tx, N_TX);
        epilogue_kernel<0><<<(N_M + 63) / 64, 256>>>(agg_m, c1_Wa + 4096, c1_ba + 64, nullptr, nullptr, h_m, N_M);
    }

    // ---- layer 2 (din = 64); only the tx destination path feeds the output ----
    {
        int din = 64;
        int effN = (din + 1) * 192;
        eff_weights_kernel<<<(effN + 255) / 256, 256>>>(
            c2_Wq, c2_bq, c2_Wk, c2_bk, c2_Wv, c2_bv, c2_a_rel, c2_m_rel, WA, bA, din);
        eff_weights_kernel<<<(effN + 255) / 256, 256>>>(
            c2_Wq + din * 64, c2_bq + 64, c2_Wk + din * 64, c2_bk + 64,
            c2_Wv + din * 64, c2_bv + 64, c2_a_rel + 1024, c2_m_rel + 1024, WB, bB, din);
        // tx needs only Q (cols 0..63); m needs only Khat/Vhat (cols 64..191)
        gemm_kernel<<<dim3((N_TX + 63) / 64, 1), 256>>>(h_tx, N_TX, din, WA, bA, proj_tx, 0);
        gemm_kernel<<<dim3((N_M + 63) / 64, 2), 256>>>(h_m, N_M, din, WB, bB, proj_m, 64);
        attn_kernel<<<(N_TX + 7) / 8, 256>>>(proj_m, proj_tx, rowptr1, srcs1, c2_p_rel + 4, agg_tx, N_TX);
        // skip-mix epilogue, in place on h_tx (each element read+written by the same thread)
        epilogue_kernel<1><<<(N_TX + 63) / 64, 256>>>(agg_tx, c2_Wa, c2_ba, h_tx, c2_skip, h_tx, N_TX);
    }

    final_kernel<<<(N_TX + 7) / 8, 256>>>(h_tx, Wc, bc, (float*)d_out, N_TX);
}

// round 5
// speedup vs baseline: 1.2273x; 1.2273x over previous
#include <cuda_runtime.h>
#include <cuda_bf16.h>
#include <cstdint>

#define NTX_MAX 100000
#define NM_MAX  20000
#define E_MAX   500000

// ---------------- scratch (static device globals; no runtime allocation) ----------------
__device__ float g_proj_tx[(size_t)NTX_MAX * 192];  // [Q | Khat | Vhat]
__device__ float g_proj_m [(size_t)NM_MAX  * 192];
__device__ float g_agg_tx [(size_t)NTX_MAX * 64];
__device__ float g_agg_m  [(size_t)NM_MAX  * 64];
__device__ float g_h_tx   [(size_t)NTX_MAX * 64];
__device__ float g_h_m    [(size_t)NM_MAX  * 64];
__device__ float g_WA[128 * 192];   // effective fused QKV weights (fp32), type tx
__device__ float g_bA[192];
__device__ float g_WB[128 * 192];   // type m
__device__ float g_bB[192];
// bf16 split buffers
__device__ __nv_bfloat16 g_txh[(size_t)NTX_MAX * 128];
__device__ __nv_bfloat16 g_txl[(size_t)NTX_MAX * 128];
__device__ __nv_bfloat16 g_mh [(size_t)NM_MAX  * 128];
__device__ __nv_bfloat16 g_ml [(size_t)NM_MAX  * 128];
__device__ __nv_bfloat16 g_WAh[128 * 192];
__device__ __nv_bfloat16 g_WAl[128 * 192];
__device__ __nv_bfloat16 g_WBh[128 * 192];
__device__ __nv_bfloat16 g_WBl[128 * 192];
__device__ __nv_bfloat16 g_Wah[64 * 64];
__device__ __nv_bfloat16 g_Wal[64 * 64];
// CSR
__device__ int g_rowptr0[NM_MAX + 1];   // dst = m   (tx->m edges)
__device__ int g_rowptr1[NTX_MAX + 1];  // dst = tx  (m->tx edges)
__device__ int g_cursor0[NM_MAX];
__device__ int g_cursor1[NTX_MAX];
__device__ int g_srcs0[E_MAX];
__device__ int g_srcs1[E_MAX];

// ---------------- CSR build ----------------
__global__ void zero_int_kernel(int* p, int n) {
    int i = blockIdx.x * blockDim.x + threadIdx.x;
    if (i < n) p[i] = 0;
}

__global__ void hist_kernel(const int* __restrict__ dst, int* __restrict__ cnt, int E) {
    int e = blockIdx.x * blockDim.x + threadIdx.x;
    if (e < E) atomicAdd(&cnt[dst[e]], 1);
}

// Single-block exclusive scan; writes rowptr[0..n] and cursor[i]=rowptr[i].
__global__ void scan_kernel(const int* __restrict__ cnt, int* __restrict__ rowptr,
                            int* __restrict__ cursor, int n) {
    __shared__ int ssum[1024];
    int tid = threadIdx.x;
    int chunk = (n + 1023) / 1024;
    int start = tid * chunk;
    int end = start + chunk; if (end > n) end = n; if (start > n) start = n;
    int s = 0;
    for (int i = start; i < end; i++) s += cnt[i];
    ssum[tid] = s;
    __syncthreads();
    for (int off = 1; off < 1024; off <<= 1) {
        int v = (tid >= off) ? ssum[tid - off] : 0;
        __syncthreads();
        ssum[tid] += v;
        __syncthreads();
    }
    int run = (tid == 0) ? 0 : ssum[tid - 1];
    for (int i = start; i < end; i++) {
        int c = cnt[i];
        rowptr[i] = run;
        cursor[i] = run;
        run += c;
    }
    if (tid == 1023) rowptr[n] = run;
}

__global__ void scatter_kernel(const int* __restrict__ src, const int* __restrict__ dst,
                               int* __restrict__ cursor, int* __restrict__ srcs_out, int E) {
    int e = blockIdx.x * blockDim.x + threadIdx.x;
    if (e < E) {
        int p = atomicAdd(&cursor[dst[e]], 1);
        srcs_out[p] = src[e];
    }
}

// ---------------- effective fused weights (fp32) ----------------
__global__ void eff_weights_kernel(const float* __restrict__ Wq, const float* __restrict__ bq,
                                   const float* __restrict__ Wk, const float* __restrict__ bk,
                                   const float* __restrict__ Wv, const float* __restrict__ bv,
                                   const float* __restrict__ a_rel, const float* __restrict__ m_rel,
                                   float* __restrict__ Wout, float* __restrict__ bout, int din) {
    int idx = blockIdx.x * blockDim.x + threadIdx.x;
    int total = (din + 1) * 192;
    if (idx >= total) return;
    int i = idx / 192, c = idx % 192;
    bool isBias = (i == din);
    float val;
    if (c < 64) {
        val = isBias ? bq[c] : Wq[i * 64 + c];
    } else {
        int cc = c - 64;
        bool isV = (cc >= 64);
        if (isV) cc -= 64;
        int h = cc >> 4, e = cc & 15;
        const float* rel  = isV ? m_rel : a_rel;
        const float* Wsrc = isV ? Wv : Wk;
        const float* bsrc = isV ? bv : bk;
        float s = 0.f;
        #pragma unroll
        for (int d = 0; d < 16; d++) {
            float w = isBias ? bsrc[h * 16 + d] : Wsrc[i * 64 + h * 16 + d];
            s += w * rel[h * 256 + d * 16 + e];
        }
        val = s;
    }
    if (isBias) bout[c] = val;
    else        Wout[i * 192 + c] = val;
}

// ---------------- bf16 hi/lo split (optional exact gelu first) ----------------
template <int GELU>
__global__ __launch_bounds__(256) void split_kernel(const float* __restrict__ in,
                                                    __nv_bfloat16* __restrict__ hi,
                                                    __nv_bfloat16* __restrict__ lo, int n) {
    int i = blockIdx.x * blockDim.x + threadIdx.x;
    if (i >= n) return;
    float v = in[i];
    if (GELU) v = 0.5f * v * (1.f + erff(v * 0.70710678118654752f));
    __nv_bfloat16 h = __float2bfloat16_rn(v);
    hi[i] = h;
    lo[i] = __float2bfloat16_rn(v - __bfloat162float(h));
}

// ---------------- tensor-core GEMM (bf16 3-split, fp32 accumulate) ----------------
// C[N, cols] = (Ah+Al)[N,DIN] @ (Bh+Bl)[DIN, ldb] (+bias) with post-op.
// Block tile 128x64, 8 warps of 32x32, K-chunk 32.
__device__ __forceinline__ void ldsm_x4(uint32_t* r, uint32_t addr) {
    asm volatile("ldmatrix.sync.aligned.m8n8.x4.shared.b16 {%0,%1,%2,%3}, [%4];"
        : "=r"(r[0]), "=r"(r[1]), "=r"(r[2]), "=r"(r[3]) : "r"(addr));
}
__device__ __forceinline__ void ldsm_x4_t(uint32_t* r, uint32_t addr) {
    asm volatile("ldmatrix.sync.aligned.m8n8.x4.trans.shared.b16 {%0,%1,%2,%3}, [%4];"
        : "=r"(r[0]), "=r"(r[1]), "=r"(r[2]), "=r"(r[3]) : "r"(addr));
}
__device__ __forceinline__ void mma_bf16(float* c, const uint32_t* a, uint32_t b0, uint32_t b1) {
    asm volatile("mma.sync.aligned.m16n8k16.row.col.f32.bf16.bf16.f32 "
        "{%0,%1,%2,%3}, {%4,%5,%6,%7}, {%8,%9}, {%0,%1,%2,%3};"
        : "+f"(c[0]), "+f"(c[1]), "+f"(c[2]), "+f"(c[3])
        : "r"(a[0]), "r"(a[1]), "r"(a[2]), "r"(a[3]), "r"(b0), "r"(b1));
}

#define AS_STRIDE 40   // 32 + 8 pad (bf16 elems): conflict-free ldmatrix
#define BS_STRIDE 72   // 64 + 8 pad

// POST: 0 = bias only, 1 = bias+relu, 2 = bias + skip-mix (a*o + (1-a)*x_in)
template <int POST>
__global__ __launch_bounds__(256) void mma_gemm_kernel(
    const __nv_bfloat16* __restrict__ Ah, const __nv_bfloat16* __restrict__ Al,
    int N, int DIN,
    const __nv_bfloat16* __restrict__ Bh, const __nv_bfloat16* __restrict__ Bl,
    int ldb, int col0,
    const float* __restrict__ bias,
    float* __restrict__ outp, int ldo,
    const float* __restrict__ x_in, const float* __restrict__ skipv) {
    __shared__ __nv_bfloat16 As[2][128 * AS_STRIDE];
    __shared__ __nv_bfloat16 Bs[2][32 * BS_STRIDE];

    int t = threadIdx.x;
    int w = t >> 5, lane = t & 31;
    int row0 = blockIdx.x * 128;
    int colW = col0 + blockIdx.y * 64;

    int mbase = (w >> 1) * 32;
    int nbase = (w & 1) * 32;
    int lrow = lane & 15;
    int lcolo = (lane >> 4) * 8;

    uint32_t a_base0 = (uint32_t)__cvta_generic_to_shared(&As[0][0]);
    uint32_t a_base1 = (uint32_t)__cvta_generic_to_shared(&As[1][0]);
    uint32_t b_base0 = (uint32_t)__cvta_generic_to_shared(&Bs[0][0]);
    uint32_t b_base1 = (uint32_t)__cvta_generic_to_shared(&Bs[1][0]);

    float acc[2][4][4];
    #pragma unroll
    for (int i = 0; i < 2; i++)
        #pragma unroll
        for (int j = 0; j < 4; j++)
            #pragma unroll
            for (int q = 0; q < 4; q++) acc[i][j][q] = 0.f;

    for (int k0 = 0; k0 < DIN; k0 += 32) {
        // load A: 2 splits x 512 uint4 (128 rows x 32 cols)
        #pragma unroll
        for (int ii = 0; ii < 4; ii++) {
            int i = t + ii * 256;
            int sp = i >> 9, idx = i & 511;
            int r = idx >> 2, quad = idx & 3;
            int grow = row0 + r;
            uint4 val = make_uint4(0u, 0u, 0u, 0u);
            const __nv_bfloat16* Aside = sp ? Al : Ah;
            if (grow < N)
                val = *(const uint4*)(Aside + (size_t)grow * DIN + k0 + quad * 8);
            *(uint4*)(&As[sp][r * AS_STRIDE + quad * 8]) = val;
        }
        // load B: 2 splits x 256 uint4 (32 rows x 64 cols)
        #pragma unroll
        for (int ii = 0; ii < 2; ii++) {
            int i = t + ii * 256;
            int sp = i >> 8, idx = i & 255;
            int r = idx >> 3, oct = idx & 7;
            const __nv_bfloat16* Bside = sp ? Bl : Bh;
            *(uint4*)(&Bs[sp][r * BS_STRIDE + oct * 8]) =
                *(const uint4*)(Bside + (size_t)(k0 + r) * ldb + colW + oct * 8);
        }
        __syncthreads();

        #pragma unroll
        for (int kb = 0; kb < 32; kb += 16) {
            uint32_t ah[2][4], al[2][4], bh[2][4], bl[2][4];
            #pragma unroll
            for (int i = 0; i < 2; i++) {
                uint32_t off = (uint32_t)(((mbase + i * 16 + lrow) * AS_STRIDE + kb + lcolo) * 2);
                ldsm_x4(ah[i], a_base0 + off);
                ldsm_x4(al[i], a_base1 + off);
            }
            #pragma unroll
            for (int j2 = 0; j2 < 2; j2++) {
                uint32_t off = (uint32_t)(((kb + lrow) * BS_STRIDE + nbase + j2 * 16 + lcolo) * 2);
                ldsm_x4_t(bh[j2], b_base0 + off);
                ldsm_x4_t(bl[j2], b_base1 + off);
            }
            #pragma unroll
            for (int i = 0; i < 2; i++)
                #pragma unroll
                for (int j = 0; j < 4; j++) {
                    int j2 = j >> 1, o = (j & 1) * 2;
                    mma_bf16(acc[i][j], ah[i], bh[j2][o], bh[j2][o + 1]);
                    mma_bf16(acc[i][j], ah[i], bl[j2][o], bl[j2][o + 1]);
                    mma_bf16(acc[i][j], al[i], bh[j2][o], bh[j2][o + 1]);
                }
        }
        __syncthreads();
    }

    // epilogue
    int g = lane >> 2, tq = lane & 3;
    float amix = 0.f;
    if (POST == 2) amix = 1.f / (1.f + __expf(-skipv[0]));
    #pragma unroll
    for (int i = 0; i < 2; i++) {
        #pragma unroll
        for (int j = 0; j < 4; j++) {
            int colg = colW + nbase + j * 8 + tq * 2;
            float b0 = bias[colg], b1 = bias[colg + 1];
            #pragma unroll
            for (int half = 0; half < 2; half++) {
                int row = row0 + mbase + i * 16 + g + half * 8;
                if (row < N) {
                    float o0 = acc[i][j][half * 2 + 0] + b0;
                    float o1 = acc[i][j][half * 2 + 1] + b1;
                    if (POST == 1) { o0 = fmaxf(o0, 0.f); o1 = fmaxf(o1, 0.f); }
                    if (POST == 2) {
                        o0 = amix * o0 + (1.f - amix) * x_in[(size_t)row * 64 + colg];
                        o1 = amix * o1 + (1.f - amix) * x_in[(size_t)row * 64 + colg + 1];
                    }
                    float2 ov = make_float2(o0, o1);
                    *(float2*)(outp + (size_t)row * ldo + colg) = ov;
                }
            }
        }
    }
}

// ---------------- attention: warp per dst node, float2 per lane ----------------
// lane owns channels {2*lane, 2*lane+1}; head h = lane>>3; reduce over lane&7.
__global__ __launch_bounds__(256) void attn_kernel(
    const float* __restrict__ projS, const float* __restrict__ projD,
    const int* __restrict__ rowptr, const int* __restrict__ srcs,
    const float* __restrict__ p_rel, float* __restrict__ agg, int n_dst) {
    int w = threadIdx.x >> 5, lane = threadIdx.x & 31;
    int dst = blockIdx.x * 8 + w;
    if (dst >= n_dst) return;
    float2 q = *(const float2*)(projD + (size_t)dst * 192 + 2 * lane);
    float pr = p_rel[lane >> 3] * 0.25f;   // /SQRT_D folded
    float ax = 0.f, ay = 0.f, den = 0.f;
    int beg = rowptr[dst], end = rowptr[dst + 1];
    int i = beg;
    for (; i + 1 < end; i += 2) {
        int s0 = srcs[i], s1 = srcs[i + 1];
        const float* p0 = projS + (size_t)s0 * 192;
        const float* p1 = projS + (size_t)s1 * 192;
        float2 k0 = *(const float2*)(p0 + 64 + 2 * lane);
        float2 v0 = *(const float2*)(p0 + 128 + 2 * lane);
        float2 k1 = *(const float2*)(p1 + 64 + 2 * lane);
        float2 v1 = *(const float2*)(p1 + 128 + 2 * lane);
        float t0 = q.x * k0.x + q.y * k0.y;
        float t1 = q.x * k1.x + q.y * k1.y;
        t0 += __shfl_xor_sync(0xffffffffu, t0, 4);
        t1 += __shfl_xor_sync(0xffffffffu, t1, 4);
        t0 += __shfl_xor_sync(0xffffffffu, t0, 2);
        t1 += __shfl_xor_sync(0xffffffffu, t1, 2);
        t0 += __shfl_xor_sync(0xffffffffu, t0, 1);
        t1 += __shfl_xor_sync(0xffffffffu, t1, 1);
        float e0 = __expf(t0 * pr);
        float e1 = __expf(t1 * pr);
        ax = fmaf(e0, v0.x, ax); ay = fmaf(e0, v0.y, ay); den += e0;
        ax = fmaf(e1, v1.x, ax); ay = fmaf(e1, v1.y, ay); den += e1;
    }
    if (i < end) {
        int s = srcs[i];
        const float* ps = projS + (size_t)s * 192;
        float2 k = *(const float2*)(ps + 64 + 2 * lane);
        float2 v = *(const float2*)(ps + 128 + 2 * lane);
        float tt = q.x * k.x + q.y * k.y;
        tt += __shfl_xor_sync(0xffffffffu, tt, 4);
        tt += __shfl_xor_sync(0xffffffffu, tt, 2);
        tt += __shfl_xor_sync(0xffffffffu, tt, 1);
        float e = __expf(tt * pr);
        ax = fmaf(e, v.x, ax); ay = fmaf(e, v.y, ay); den += e;
    }
    float inv = 1.f / (den + 1e-16f);
    float2 o = make_float2(ax * inv, ay * inv);
    *(float2*)(agg + (size_t)dst * 64 + 2 * lane) = o;
}

// ---------------- final logits ----------------
__global__ __launch_bounds__(256) void final_kernel(
    const float* __restrict__ h, const float* __restrict__ Wc, const float* __restrict__ bc,
    float* __restrict__ out, int N) {
    int warp = (blockIdx.x * blockDim.x + threadIdx.x) >> 5;
    int lane = threadIdx.x & 31;
    if (warp >= N) return;
    float s = h[(size_t)warp * 64 + lane] * Wc[lane] + h[(size_t)warp * 64 + 32 + lane] * Wc[32 + lane];
    #pragma unroll
    for (int off = 16; off; off >>= 1) s += __shfl_xor_sync(0xffffffffu, s, off);
    if (lane == 0) out[warp] = s + bc[0];
}

// ---------------- launch ----------------
extern "C" void kernel_launch(void* const* d_in, const int* in_sizes, int n_in,
                              void* d_out, int out_size) {
    (void)n_in; (void)out_size;
    int ebase, wbase;
    if (in_sizes[2] > 100000) { ebase = 2;  wbase = 6; }
    else                      { ebase = 27; wbase = 2; }

    const float* x_tx = (const float*)d_in[0];
    const float* x_m  = (const float*)d_in[1];
    const int* tm_src = (const int*)d_in[ebase + 0];
    const int* tm_dst = (const int*)d_in[ebase + 1];
    const int* mt_src = (const int*)d_in[ebase + 2];
    const int* mt_dst = (const int*)d_in[ebase + 3];

    const float* c1_Wk    = (const float*)d_in[wbase + 0];
    const float* c1_bk    = (const float*)d_in[wbase + 1];
    const float* c1_Wq    = (const float*)d_in[wbase + 2];
    const float* c1_bq    = (const float*)d_in[wbase + 3];
    const float* c1_Wv    = (const float*)d_in[wbase + 4];
    const float* c1_bv    = (const float*)d_in[wbase + 5];
    const float* c1_a_rel = (const float*)d_in[wbase + 6];
    const float* c1_m_rel = (const float*)d_in[wbase + 7];
    const float* c1_p_rel = (const float*)d_in[wbase + 8];
    const float* c1_Wa    = (const float*)d_in[wbase + 9];
    const float* c1_ba    = (const float*)d_in[wbase + 10];
    const float* c2_Wk    = (const float*)d_in[wbase + 11];
    const float* c2_bk    = (const float*)d_in[wbase + 12];
    const float* c2_Wq    = (const float*)d_in[wbase + 13];
    const float* c2_bq    = (const float*)d_in[wbase + 14];
    const float* c2_Wv    = (const float*)d_in[wbase + 15];
    const float* c2_bv    = (const float*)d_in[wbase + 16];
    const float* c2_a_rel = (const float*)d_in[wbase + 17];
    const float* c2_m_rel = (const float*)d_in[wbase + 18];
    const float* c2_p_rel = (const float*)d_in[wbase + 19];
    const float* c2_Wa    = (const float*)d_in[wbase + 20];
    const float* c2_ba    = (const float*)d_in[wbase + 21];
    const float* c2_skip  = (const float*)d_in[wbase + 22];
    const float* Wc       = (const float*)d_in[wbase + 23];
    const float* bc       = (const float*)d_in[wbase + 24];

    int N_TX = in_sizes[0] / 128;
    int N_M  = in_sizes[1] / 128;
    int E0 = in_sizes[ebase + 1];
    int E1 = in_sizes[ebase + 3];

    void* p;
    float *proj_tx, *proj_m, *agg_tx, *agg_m, *h_tx, *h_m, *WA, *bA, *WB, *bB;
    __nv_bfloat16 *txh, *txl, *mh, *ml, *WAh, *WAl, *WBh, *WBl, *Wah, *Wal;
    int *rowptr0, *rowptr1, *cursor0, *cursor1, *srcs0, *srcs1;
    cudaGetSymbolAddress(&p, g_proj_tx); proj_tx = (float*)p;
    cudaGetSymbolAddress(&p, g_proj_m);  proj_m  = (float*)p;
    cudaGetSymbolAddress(&p, g_agg_tx);  agg_tx  = (float*)p;
    cudaGetSymbolAddress(&p, g_agg_m);   agg_m   = (float*)p;
    cudaGetSymbolAddress(&p, g_h_tx);    h_tx    = (float*)p;
    cudaGetSymbolAddress(&p, g_h_m);     h_m     = (float*)p;
    cudaGetSymbolAddress(&p, g_WA);      WA      = (float*)p;
    cudaGetSymbolAddress(&p, g_bA);      bA      = (float*)p;
    cudaGetSymbolAddress(&p, g_WB);      WB      = (float*)p;
    cudaGetSymbolAddress(&p, g_bB);      bB      = (float*)p;
    cudaGetSymbolAddress(&p, g_txh);     txh     = (__nv_bfloat16*)p;
    cudaGetSymbolAddress(&p, g_txl);     txl     = (__nv_bfloat16*)p;
    cudaGetSymbolAddress(&p, g_mh);      mh      = (__nv_bfloat16*)p;
    cudaGetSymbolAddress(&p, g_ml);      ml      = (__nv_bfloat16*)p;
    cudaGetSymbolAddress(&p, g_WAh);     WAh     = (__nv_bfloat16*)p;
    cudaGetSymbolAddress(&p, g_WAl);     WAl     = (__nv_bfloat16*)p;
    cudaGetSymbolAddress(&p, g_WBh);     WBh     = (__nv_bfloat16*)p;
    cudaGetSymbolAddress(&p, g_WBl);     WBl     = (__nv_bfloat16*)p;
    cudaGetSymbolAddress(&p, g_Wah);     Wah     = (__nv_bfloat16*)p;
    cudaGetSymbolAddress(&p, g_Wal);     Wal     = (__nv_bfloat16*)p;
    cudaGetSymbolAddress(&p, g_rowptr0); rowptr0 = (int*)p;
    cudaGetSymbolAddress(&p, g_rowptr1); rowptr1 = (int*)p;
    cudaGetSymbolAddress(&p, g_cursor0); cursor0 = (int*)p;
    cudaGetSymbolAddress(&p, g_cursor1); cursor1 = (int*)p;
    cudaGetSymbolAddress(&p, g_srcs0);   srcs0   = (int*)p;
    cudaGetSymbolAddress(&p, g_srcs1);   srcs1   = (int*)p;

    int gbTX = (N_TX + 127) / 128;
    int gbM  = (N_M + 127) / 128;

    // ---- CSR build ----
    zero_int_kernel<<<(N_M + 255) / 256, 256>>>(cursor0, N_M);
    zero_int_kernel<<<(N_TX + 255) / 256, 256>>>(cursor1, N_TX);
    hist_kernel<<<(E0 + 255) / 256, 256>>>(tm_dst, cursor0, E0);
    hist_kernel<<<(E1 + 255) / 256, 256>>>(mt_dst, cursor1, E1);
    scan_kernel<<<1, 1024>>>(cursor0, rowptr0, cursor0, N_M);
    scan_kernel<<<1, 1024>>>(cursor1, rowptr1, cursor1, N_TX);
    scatter_kernel<<<(E0 + 255) / 256, 256>>>(tm_src, tm_dst, cursor0, srcs0, E0);
    scatter_kernel<<<(E1 + 255) / 256, 256>>>(mt_src, mt_dst, cursor1, srcs1, E1);

    // ---- layer 1 (din = 128) ----
    {
        int din = 128;
        int effN = (din + 1) * 192;
        eff_weights_kernel<<<(effN + 255) / 256, 256>>>(
            c1_Wq, c1_bq, c1_Wk, c1_bk, c1_Wv, c1_bv, c1_a_rel, c1_m_rel, WA, bA, din);
        eff_weights_kernel<<<(effN + 255) / 256, 256>>>(
            c1_Wq + din * 64, c1_bq + 64, c1_Wk + din * 64, c1_bk + 64,
            c1_Wv + din * 64, c1_bv + 64, c1_a_rel + 1024, c1_m_rel + 1024, WB, bB, din);
        split_kernel<0><<<(din * 192 + 255) / 256, 256>>>(WA, WAh, WAl, din * 192);
        split_kernel<0><<<(din * 192 + 255) / 256, 256>>>(WB, WBh, WBl, din * 192);
        int nx = N_TX * 128, nm = N_M * 128;
        split_kernel<0><<<(nx + 255) / 256, 256>>>(x_tx, txh, txl, nx);
        split_kernel<0><<<(nm + 255) / 256, 256>>>(x_m, mh, ml, nm);
        mma_gemm_kernel<0><<<dim3(gbTX, 3), 256>>>(txh, txl, N_TX, din, WAh, WAl, 192, 0,
                                                   bA, proj_tx, 192, nullptr, nullptr);
        mma_gemm_kernel<0><<<dim3(gbM, 3), 256>>>(mh, ml, N_M, din, WBh, WBl, 192, 0,
                                                  bB, proj_m, 192, nullptr, nullptr);
        attn_kernel<<<(N_M + 7) / 8, 256>>>(proj_tx, proj_m, rowptr0, srcs0, c1_p_rel, agg_m, N_M);
        attn_kernel<<<(N_TX + 7) / 8, 256>>>(proj_m, proj_tx, rowptr1, srcs1, c1_p_rel + 4, agg_tx, N_TX);
        // epilogue tx: h_tx = relu( gelu(agg_tx) @ Wa0 + ba0 )
        split_kernel<1><<<(N_TX * 64 + 255) / 256, 256>>>(agg_tx, txh, txl, N_TX * 64);
        split_kernel<0><<<(4096 + 255) / 256, 256>>>(c1_Wa, Wah, Wal, 4096);
        mma_gemm_kernel<1><<<dim3(gbTX, 1), 256>>>(txh, txl, N_TX, 64, Wah, Wal, 64, 0,
                                                   c1_ba, h_tx, 64, nullptr, nullptr);
        // epilogue m
        split_kernel<1><<<(N_M * 64 + 255) / 256, 256>>>(agg_m, mh, ml, N_M * 64);
        split_kernel<0><<<(4096 + 255) / 256, 256>>>(c1_Wa + 4096, Wah, Wal, 4096);
        mma_gemm_kernel<1><<<dim3(gbM, 1), 256>>>(mh, ml, N_M, 64, Wah, Wal, 64, 0,
                                                  c1_ba + 64, h_m, 64, nullptr, nullptr);
    }

    // ---- layer 2 (din = 64); only tx destination feeds the output ----
    {
        int din = 64;
        int effN = (din + 1) * 192;
        eff_weights_kernel<<<(effN + 255) / 256, 256>>>(
            c2_Wq, c2_bq, c2_Wk, c2_bk, c2_Wv, c2_bv, c2_a_rel, c2_m_rel, WA, bA, din);
        eff_weights_kernel<<<(effN + 255) / 256, 256>>>(
            c2_Wq + din * 64, c2_bq + 64, c2_Wk + din * 64, c2_bk + 64,
            c2_Wv + din * 64, c2_bv + 64, c2_a_rel + 1024, c2_m_rel + 1024, WB, bB, din);
        split_kernel<0><<<(din * 192 + 255) / 256, 256>>>(WA, WAh, WAl, din * 192);
        split_kernel<0><<<(din * 192 + 255) / 256, 256>>>(WB, WBh, WBl, din * 192);
        split_kernel<0><<<(N_TX * 64 + 255) / 256, 256>>>(h_tx, txh, txl, N_TX * 64);
        split_kernel<0><<<(N_M * 64 + 255) / 256, 256>>>(h_m, mh, ml, N_M * 64);
        // tx needs only Q (cols 0..63); m needs only Khat/Vhat (cols 64..191)
        mma_gemm_kernel<0><<<dim3(gbTX, 1), 256>>>(txh, txl, N_TX, din, WAh, WAl, 192, 0,
                                                   bA, proj_tx, 192, nullptr, nullptr);
        mma_gemm_kernel<0><<<dim3(gbM, 2), 256>>>(mh, ml, N_M, din, WBh, WBl, 192, 64,
                                                  bB, proj_m, 192, nullptr, nullptr);
        attn_kernel<<<(N_TX + 7) / 8, 256>>>(proj_m, proj_tx, rowptr1, srcs1, c2_p_rel + 4, agg_tx, N_TX);
        // skip-mix epilogue, in place on h_tx (same thread reads x_in then writes)
        split_kernel<1><<<(N_TX * 64 + 255) / 256, 256>>>(agg_tx, txh, txl, N_TX * 64);
        split_kernel<0><<<(4096 + 255) / 256, 256>>>(c2_Wa, Wah, Wal, 4096);
        mma_gemm_kernel<2><<<dim3(gbTX, 1), 256>>>(txh, txl, N_TX, 64, Wah, Wal, 64, 0,
                                                   c2_ba, h_tx, 64, h_tx, c2_skip);
    }

    final_kernel<<<(N_TX + 7) / 8, 256>>>(h_tx, Wc, bc, (float*)d_out, N_TX);
}

// round 6
// speedup vs baseline: 1.3697x; 1.1161x over previous
#include <cuda_runtime.h>
#include <cuda_bf16.h>
#include <cstdint>

#define NTX_MAX 100000
#define NM_MAX  20000
#define E_MAX   500000

// ---------------- scratch (static device globals; no runtime allocation) ----------------
__device__ float g_proj_tx[(size_t)NTX_MAX * 192];  // [Q | Khat | Vhat]
__device__ float g_proj_m [(size_t)NM_MAX  * 192];
__device__ float g_agg_tx [(size_t)NTX_MAX * 64];
__device__ float g_agg_m  [(size_t)NM_MAX  * 64];
__device__ float g_h_tx   [(size_t)NTX_MAX * 64];
__device__ float g_h_m    [(size_t)NM_MAX  * 64];
__device__ float g_WA[128 * 192];   // effective fused QKV weights (fp32), type tx
__device__ float g_bA[192];
__device__ float g_WB[128 * 192];   // type m
__device__ float g_bB[192];
// CSR
__device__ int g_rowptr0[NM_MAX + 1];   // dst = m   (tx->m edges)
__device__ int g_rowptr1[NTX_MAX + 1];  // dst = tx  (m->tx edges)
__device__ int g_cursor0[NM_MAX];
__device__ int g_cursor1[NTX_MAX];
__device__ int g_srcs0[E_MAX];
__device__ int g_srcs1[E_MAX];

// ---------------- CSR build ----------------
__global__ void zero_int_kernel(int* p, int n) {
    int i = blockIdx.x * blockDim.x + threadIdx.x;
    if (i < n) p[i] = 0;
}

__global__ void hist_kernel(const int* __restrict__ dst, int* __restrict__ cnt, int E) {
    int e = blockIdx.x * blockDim.x + threadIdx.x;
    if (e < E) atomicAdd(&cnt[dst[e]], 1);
}

// Single-block exclusive scan; writes rowptr[0..n] and cursor[i]=rowptr[i].
__global__ void scan_kernel(const int* __restrict__ cnt, int* __restrict__ rowptr,
                            int* __restrict__ cursor, int n) {
    __shared__ int ssum[1024];
    int tid = threadIdx.x;
    int chunk = (n + 1023) / 1024;
    int start = tid * chunk;
    int end = start + chunk; if (end > n) end = n; if (start > n) start = n;
    int s = 0;
    for (int i = start; i < end; i++) s += cnt[i];
    ssum[tid] = s;
    __syncthreads();
    for (int off = 1; off < 1024; off <<= 1) {
        int v = (tid >= off) ? ssum[tid - off] : 0;
        __syncthreads();
        ssum[tid] += v;
        __syncthreads();
    }
    int run = (tid == 0) ? 0 : ssum[tid - 1];
    for (int i = start; i < end; i++) {
        int c = cnt[i];
        rowptr[i] = run;
        cursor[i] = run;
        run += c;
    }
    if (tid == 1023) rowptr[n] = run;
}

__global__ void scatter_kernel(const int* __restrict__ src, const int* __restrict__ dst,
                               int* __restrict__ cursor, int* __restrict__ srcs_out, int E) {
    int e = blockIdx.x * blockDim.x + threadIdx.x;
    if (e < E) {
        int p = atomicAdd(&cursor[dst[e]], 1);
        srcs_out[p] = src[e];
    }
}

// ---------------- effective fused weights (fp32) ----------------
__global__ void eff_weights_kernel(const float* __restrict__ Wq, const float* __restrict__ bq,
                                   const float* __restrict__ Wk, const float* __restrict__ bk,
                                   const float* __restrict__ Wv, const float* __restrict__ bv,
                                   const float* __restrict__ a_rel, const float* __restrict__ m_rel,
                                   float* __restrict__ Wout, float* __restrict__ bout, int din) {
    int idx = blockIdx.x * blockDim.x + threadIdx.x;
    int total = (din + 1) * 192;
    if (idx >= total) return;
    int i = idx / 192, c = idx % 192;
    bool isBias = (i == din);
    float val;
    if (c < 64) {
        val = isBias ? bq[c] : Wq[i * 64 + c];
    } else {
        int cc = c - 64;
        bool isV = (cc >= 64);
        if (isV) cc -= 64;
        int h = cc >> 4, e = cc & 15;
        const float* rel  = isV ? m_rel : a_rel;
        const float* Wsrc = isV ? Wv : Wk;
        const float* bsrc = isV ? bv : bk;
        float s = 0.f;
        #pragma unroll
        for (int d = 0; d < 16; d++) {
            float w = isBias ? bsrc[h * 16 + d] : Wsrc[i * 64 + h * 16 + d];
            s += w * rel[h * 256 + d * 16 + e];
        }
        val = s;
    }
    if (isBias) bout[c] = val;
    else        Wout[i * 192 + c] = val;
}

// ---------------- tensor-core GEMM (fused fp32->bf16 3-split, fp32 accumulate) ----------------
// C[N, cols] = gelu?(A)[N,DIN] @ B[DIN, ldb] (+bias) with post-op.
// A, B are fp32 in gmem; hi/lo bf16 split happens during smem staging.
// Block tile 128x64, 8 warps of 32x32, K-chunk 32.
__device__ __forceinline__ void ldsm_x4(uint32_t* r, uint32_t addr) {
    asm volatile("ldmatrix.sync.aligned.m8n8.x4.shared.b16 {%0,%1,%2,%3}, [%4];"
        : "=r"(r[0]), "=r"(r[1]), "=r"(r[2]), "=r"(r[3]) : "r"(addr));
}
__device__ __forceinline__ void ldsm_x4_t(uint32_t* r, uint32_t addr) {
    asm volatile("ldmatrix.sync.aligned.m8n8.x4.trans.shared.b16 {%0,%1,%2,%3}, [%4];"
        : "=r"(r[0]), "=r"(r[1]), "=r"(r[2]), "=r"(r[3]) : "r"(addr));
}
__device__ __forceinline__ void mma_bf16(float* c, const uint32_t* a, uint32_t b0, uint32_t b1) {
    asm volatile("mma.sync.aligned.m16n8k16.row.col.f32.bf16.bf16.f32 "
        "{%0,%1,%2,%3}, {%4,%5,%6,%7}, {%8,%9}, {%0,%1,%2,%3};"
        : "+f"(c[0]), "+f"(c[1]), "+f"(c[2]), "+f"(c[3])
        : "r"(a[0]), "r"(a[1]), "r"(a[2]), "r"(a[3]), "r"(b0), "r"(b1));
}

__device__ __forceinline__ void split2(float x, float y, uint32_t& hi, uint32_t& lo) {
    __nv_bfloat16 hx = __float2bfloat16_rn(x), hy = __float2bfloat16_rn(y);
    __nv_bfloat16 lx = __float2bfloat16_rn(x - __bfloat162float(hx));
    __nv_bfloat16 ly = __float2bfloat16_rn(y - __bfloat162float(hy));
    __nv_bfloat162 h2 = __halves2bfloat162(hx, hy);
    __nv_bfloat162 l2 = __halves2bfloat162(lx, ly);
    hi = *(uint32_t*)&h2;
    lo = *(uint32_t*)&l2;
}

__device__ __forceinline__ float gelu_exact(float v) {
    return 0.5f * v * (1.f + erff(v * 0.70710678118654752f));
}

#define AS_STRIDE 40   // 32 + 8 pad (bf16 elems): conflict-free ldmatrix
#define BS_STRIDE 72   // 64 + 8 pad

// POST: 0 = bias only, 1 = bias+relu, 2 = bias + skip-mix (a*o + (1-a)*x_in)
// AGELU: apply exact gelu to A elements while staging.
template <int POST, int AGELU>
__global__ __launch_bounds__(256) void mma_gemm_kernel(
    const float* __restrict__ A, int N, int DIN,
    const float* __restrict__ B, int ldb, int col0,
    const float* __restrict__ bias,
    float* __restrict__ outp, int ldo,
    const float* __restrict__ x_in, const float* __restrict__ skipv) {
    __shared__ __nv_bfloat16 As[2][128 * AS_STRIDE];
    __shared__ __nv_bfloat16 Bs[2][32 * BS_STRIDE];

    int t = threadIdx.x;
    int w = t >> 5, lane = t & 31;
    int row0 = blockIdx.x * 128;
    int colW = col0 + blockIdx.y * 64;

    int mbase = (w >> 1) * 32;
    int nbase = (w & 1) * 32;
    int lrow = lane & 15;
    int lcolo = (lane >> 4) * 8;

    uint32_t a_base0 = (uint32_t)__cvta_generic_to_shared(&As[0][0]);
    uint32_t a_base1 = (uint32_t)__cvta_generic_to_shared(&As[1][0]);
    uint32_t b_base0 = (uint32_t)__cvta_generic_to_shared(&Bs[0][0]);
    uint32_t b_base1 = (uint32_t)__cvta_generic_to_shared(&Bs[1][0]);

    float acc[2][4][4];
    #pragma unroll
    for (int i = 0; i < 2; i++)
        #pragma unroll
        for (int j = 0; j < 4; j++)
            #pragma unroll
            for (int q = 0; q < 4; q++) acc[i][j][q] = 0.f;

    for (int k0 = 0; k0 < DIN; k0 += 32) {
        // stage A: 128 rows x 32 cols fp32 -> split to hi/lo bf16
        #pragma unroll
        for (int ii = 0; ii < 4; ii++) {
            int idx = t + ii * 256;          // 0..1023
            int r = idx >> 3, q = idx & 7;   // row, float4-col
            int grow = row0 + r;
            float4 v = make_float4(0.f, 0.f, 0.f, 0.f);
            if (grow < N) v = *(const float4*)(A + (size_t)grow * DIN + k0 + q * 4);
            if (AGELU) {
                v.x = gelu_exact(v.x); v.y = gelu_exact(v.y);
                v.z = gelu_exact(v.z); v.w = gelu_exact(v.w);
            }
            uint32_t h0, l0, h1, l1;
            split2(v.x, v.y, h0, l0);
            split2(v.z, v.w, h1, l1);
            *(uint2*)(&As[0][r * AS_STRIDE + q * 4]) = make_uint2(h0, h1);
            *(uint2*)(&As[1][r * AS_STRIDE + q * 4]) = make_uint2(l0, l1);
        }
        // stage B: 32 rows x 64 cols fp32 -> split
        #pragma unroll
        for (int ii = 0; ii < 2; ii++) {
            int idx = t + ii * 256;           // 0..511
            int r = idx >> 4, q = idx & 15;
            float4 v = *(const float4*)(B + (size_t)(k0 + r) * ldb + colW + q * 4);
            uint32_t h0, l0, h1, l1;
            split2(v.x, v.y, h0, l0);
            split2(v.z, v.w, h1, l1);
            *(uint2*)(&Bs[0][r * BS_STRIDE + q * 4]) = make_uint2(h0, h1);
            *(uint2*)(&Bs[1][r * BS_STRIDE + q * 4]) = make_uint2(l0, l1);
        }
        __syncthreads();

        #pragma unroll
        for (int kb = 0; kb < 32; kb += 16) {
            uint32_t ah[2][4], al[2][4], bh[2][4], bl[2][4];
            #pragma unroll
            for (int i = 0; i < 2; i++) {
                uint32_t off = (uint32_t)(((mbase + i * 16 + lrow) * AS_STRIDE + kb + lcolo) * 2);
                ldsm_x4(ah[i], a_base0 + off);
                ldsm_x4(al[i], a_base1 + off);
            }
            #pragma unroll
            for (int j2 = 0; j2 < 2; j2++) {
                uint32_t off = (uint32_t)(((kb + lrow) * BS_STRIDE + nbase + j2 * 16 + lcolo) * 2);
                ldsm_x4_t(bh[j2], b_base0 + off);
                ldsm_x4_t(bl[j2], b_base1 + off);
            }
            #pragma unroll
            for (int i = 0; i < 2; i++)
                #pragma unroll
                for (int j = 0; j < 4; j++) {
                    int j2 = j >> 1, o = (j & 1) * 2;
                    mma_bf16(acc[i][j], ah[i], bh[j2][o], bh[j2][o + 1]);
                    mma_bf16(acc[i][j], ah[i], bl[j2][o], bl[j2][o + 1]);
                    mma_bf16(acc[i][j], al[i], bh[j2][o], bh[j2][o + 1]);
                }
        }
        __syncthreads();
    }

    // epilogue
    int g = lane >> 2, tq = lane & 3;
    float amix = 0.f;
    if (POST == 2) amix = 1.f / (1.f + __expf(-skipv[0]));
    #pragma unroll
    for (int i = 0; i < 2; i++) {
        #pragma unroll
        for (int j = 0; j < 4; j++) {
            int colg = colW + nbase + j * 8 + tq * 2;
            float b0 = bias[colg], b1 = bias[colg + 1];
            #pragma unroll
            for (int half = 0; half < 2; half++) {
                int row = row0 + mbase + i * 16 + g + half * 8;
                if (row < N) {
                    float o0 = acc[i][j][half * 2 + 0] + b0;
                    float o1 = acc[i][j][half * 2 + 1] + b1;
                    if (POST == 1) { o0 = fmaxf(o0, 0.f); o1 = fmaxf(o1, 0.f); }
                    if (POST == 2) {
                        o0 = amix * o0 + (1.f - amix) * x_in[(size_t)row * 64 + colg];
                        o1 = amix * o1 + (1.f - amix) * x_in[(size_t)row * 64 + colg + 1];
                    }
                    float2 ov = make_float2(o0, o1);
                    *(float2*)(outp + (size_t)row * ldo + colg) = ov;
                }
            }
        }
    }
}

// ---------------- attention: warp per dst, 8 lanes per edge, 4 edges in flight ----------------
// lane = 8*eg + sub; sub owns channels [8*sub, 8*sub+8); head = sub>>1.
// score reduction: ONE shfl_xor(1); subgroup combine at the end (xor 8, 16).
__global__ __launch_bounds__(256) void attn_kernel(
    const float* __restrict__ projS, const float* __restrict__ projD,
    const int* __restrict__ rowptr, const int* __restrict__ srcs,
    const float* __restrict__ p_rel, float* __restrict__ agg, int n_dst) {
    int w = threadIdx.x >> 5, lane = threadIdx.x & 31;
    int dst = blockIdx.x * 8 + w;
    if (dst >= n_dst) return;
    int sub = lane & 7;
    int eg = lane >> 3;
    const float* qd = projD + (size_t)dst * 192 + sub * 8;
    float4 q0 = *(const float4*)(qd);
    float4 q1 = *(const float4*)(qd + 4);
    float pr = p_rel[sub >> 1] * 0.25f;   // /SQRT_D folded
    float4 a0 = make_float4(0.f, 0.f, 0.f, 0.f);
    float4 a1 = make_float4(0.f, 0.f, 0.f, 0.f);
    float den = 0.f;
    int beg = rowptr[dst], end = rowptr[dst + 1];
    for (int i = beg; i < end; i += 4) {
        int ei = i + eg;
        bool valid = ei < end;
        int s = srcs[valid ? ei : beg];
        const float* ps = projS + (size_t)s * 192 + sub * 8;
        float4 k0 = *(const float4*)(ps + 64);
        float4 k1 = *(const float4*)(ps + 68);
        float4 v0 = *(const float4*)(ps + 128);
        float4 v1 = *(const float4*)(ps + 132);
        float part = q0.x * k0.x + q0.y * k0.y + q0.z * k0.z + q0.w * k0.w
                   + q1.x * k1.x + q1.y * k1.y + q1.z * k1.z + q1.w * k1.w;
        part += __shfl_xor_sync(0xffffffffu, part, 1);
        float e = valid ? __expf(part * pr) : 0.f;
        a0.x = fmaf(e, v0.x, a0.x); a0.y = fmaf(e, v0.y, a0.y);
        a0.z = fmaf(e, v0.z, a0.z); a0.w = fmaf(e, v0.w, a0.w);
        a1.x = fmaf(e, v1.x, a1.x); a1.y = fmaf(e, v1.y, a1.y);
        a1.z = fmaf(e, v1.z, a1.z); a1.w = fmaf(e, v1.w, a1.w);
        den += e;
    }
    // combine the 4 edge-subgroups (lanes l, l+8, l+16, l+24 share a channel slice)
    #pragma unroll
    for (int off = 8; off <= 16; off <<= 1) {
        a0.x += __shfl_xor_sync(0xffffffffu, a0.x, off);
        a0.y += __shfl_xor_sync(0xffffffffu, a0.y, off);
        a0.z += __shfl_xor_sync(0xffffffffu, a0.z, off);
        a0.w += __shfl_xor_sync(0xffffffffu, a0.w, off);
        a1.x += __shfl_xor_sync(0xffffffffu, a1.x, off);
        a1.y += __shfl_xor_sync(0xffffffffu, a1.y, off);
        a1.z += __shfl_xor_sync(0xffffffffu, a1.z, off);
        a1.w += __shfl_xor_sync(0xffffffffu, a1.w, off);
        den  += __shfl_xor_sync(0xffffffffu, den, off);
    }
    if (lane < 8) {
        float inv = 1.f / (den + 1e-16f);
        a0.x *= inv; a0.y *= inv; a0.z *= inv; a0.w *= inv;
        a1.x *= inv; a1.y *= inv; a1.z *= inv; a1.w *= inv;
        float* op = agg + (size_t)dst * 64 + sub * 8;
        *(float4*)(op) = a0;
        *(float4*)(op + 4) = a1;
    }
}

// ---------------- final logits ----------------
__global__ __launch_bounds__(256) void final_kernel(
    const float* __restrict__ h, const float* __restrict__ Wc, const float* __restrict__ bc,
    float* __restrict__ out, int N) {
    int warp = (blockIdx.x * blockDim.x + threadIdx.x) >> 5;
    int lane = threadIdx.x & 31;
    if (warp >= N) return;
    float s = h[(size_t)warp * 64 + lane] * Wc[lane] + h[(size_t)warp * 64 + 32 + lane] * Wc[32 + lane];
    #pragma unroll
    for (int off = 16; off; off >>= 1) s += __shfl_xor_sync(0xffffffffu, s, off);
    if (lane == 0) out[warp] = s + bc[0];
}

// ---------------- launch ----------------
extern "C" void kernel_launch(void* const* d_in, const int* in_sizes, int n_in,
                              void* d_out, int out_size) {
    (void)n_in; (void)out_size;
    int ebase, wbase;
    if (in_sizes[2] > 100000) { ebase = 2;  wbase = 6; }
    else                      { ebase = 27; wbase = 2; }

    const float* x_tx = (const float*)d_in[0];
    const float* x_m  = (const float*)d_in[1];
    const int* tm_src = (const int*)d_in[ebase + 0];
    const int* tm_dst = (const int*)d_in[ebase + 1];
    const int* mt_src = (const int*)d_in[ebase + 2];
    const int* mt_dst = (const int*)d_in[ebase + 3];

    const float* c1_Wk    = (const float*)d_in[wbase + 0];
    const float* c1_bk    = (const float*)d_in[wbase + 1];
    const float* c1_Wq    = (const float*)d_in[wbase + 2];
    const float* c1_bq    = (const float*)d_in[wbase + 3];
    const float* c1_Wv    = (const float*)d_in[wbase + 4];
    const float* c1_bv    = (const float*)d_in[wbase + 5];
    const float* c1_a_rel = (const float*)d_in[wbase + 6];
    const float* c1_m_rel = (const float*)d_in[wbase + 7];
    const float* c1_p_rel = (const float*)d_in[wbase + 8];
    const float* c1_Wa    = (const float*)d_in[wbase + 9];
    const float* c1_ba    = (const float*)d_in[wbase + 10];
    const float* c2_Wk    = (const float*)d_in[wbase + 11];
    const float* c2_bk    = (const float*)d_in[wbase + 12];
    const float* c2_Wq    = (const float*)d_in[wbase + 13];
    const float* c2_bq    = (const float*)d_in[wbase + 14];
    const float* c2_Wv    = (const float*)d_in[wbase + 15];
    const float* c2_bv    = (const float*)d_in[wbase + 16];
    const float* c2_a_rel = (const float*)d_in[wbase + 17];
    const float* c2_m_rel = (const float*)d_in[wbase + 18];
    const float* c2_p_rel = (const float*)d_in[wbase + 19];
    const float* c2_Wa    = (const float*)d_in[wbase + 20];
    const float* c2_ba    = (const float*)d_in[wbase + 21];
    const float* c2_skip  = (const float*)d_in[wbase + 22];
    const float* Wc       = (const float*)d_in[wbase + 23];
    const float* bc       = (const float*)d_in[wbase + 24];

    int N_TX = in_sizes[0] / 128;
    int N_M  = in_sizes[1] / 128;
    int E0 = in_sizes[ebase + 1];
    int E1 = in_sizes[ebase + 3];

    void* p;
    float *proj_tx, *proj_m, *agg_tx, *agg_m, *h_tx, *h_m, *WA, *bA, *WB, *bB;
    int *rowptr0, *rowptr1, *cursor0, *cursor1, *srcs0, *srcs1;
    cudaGetSymbolAddress(&p, g_proj_tx); proj_tx = (float*)p;
    cudaGetSymbolAddress(&p, g_proj_m);  proj_m  = (float*)p;
    cudaGetSymbolAddress(&p, g_agg_tx);  agg_tx  = (float*)p;
    cudaGetSymbolAddress(&p, g_agg_m);   agg_m   = (float*)p;
    cudaGetSymbolAddress(&p, g_h_tx);    h_tx    = (float*)p;
    cudaGetSymbolAddress(&p, g_h_m);     h_m     = (float*)p;
    cudaGetSymbolAddress(&p, g_WA);      WA      = (float*)p;
    cudaGetSymbolAddress(&p, g_bA);      bA      = (float*)p;
    cudaGetSymbolAddress(&p, g_WB);      WB      = (float*)p;
    cudaGetSymbolAddress(&p, g_bB);      bB      = (float*)p;
    cudaGetSymbolAddress(&p, g_rowptr0); rowptr0 = (int*)p;
    cudaGetSymbolAddress(&p, g_rowptr1); rowptr1 = (int*)p;
    cudaGetSymbolAddress(&p, g_cursor0); cursor0 = (int*)p;
    cudaGetSymbolAddress(&p, g_cursor1); cursor1 = (int*)p;
    cudaGetSymbolAddress(&p, g_srcs0);   srcs0   = (int*)p;
    cudaGetSymbolAddress(&p, g_srcs1);   srcs1   = (int*)p;

    int gbTX = (N_TX + 127) / 128;
    int gbM  = (N_M + 127) / 128;

    // ---- CSR build ----
    zero_int_kernel<<<(N_M + 255) / 256, 256>>>(cursor0, N_M);
    zero_int_kernel<<<(N_TX + 255) / 256, 256>>>(cursor1, N_TX);
    hist_kernel<<<(E0 + 255) / 256, 256>>>(tm_dst, cursor0, E0);
    hist_kernel<<<(E1 + 255) / 256, 256>>>(mt_dst, cursor1, E1);
    scan_kernel<<<1, 1024>>>(cursor0, rowptr0, cursor0, N_M);
    scan_kernel<<<1, 1024>>>(cursor1, rowptr1, cursor1, N_TX);
    scatter_kernel<<<(E0 + 255) / 256, 256>>>(tm_src, tm_dst, cursor0, srcs0, E0);
    scatter_kernel<<<(E1 + 255) / 256, 256>>>(mt_src, mt_dst, cursor1, srcs1, E1);

    // ---- layer 1 (din = 128) ----
    {
        int din = 128;
        int effN = (din + 1) * 192;
        eff_weights_kernel<<<(effN + 255) / 256, 256>>>(
            c1_Wq, c1_bq, c1_Wk, c1_bk, c1_Wv, c1_bv, c1_a_rel, c1_m_rel, WA, bA, din);
        eff_weights_kernel<<<(effN + 255) / 256, 256>>>(
            c1_Wq + din * 64, c1_bq + 64, c1_Wk + din * 64, c1_bk + 64,
            c1_Wv + din * 64, c1_bv + 64, c1_a_rel + 1024, c1_m_rel + 1024, WB, bB, din);
        mma_gemm_kernel<0, 0><<<dim3(gbTX, 3), 256>>>(x_tx, N_TX, din, WA, 192, 0,
                                                      bA, proj_tx, 192, nullptr, nullptr);
        mma_gemm_kernel<0, 0><<<dim3(gbM, 3), 256>>>(x_m, N_M, din, WB, 192, 0,
                                                     bB, proj_m, 192, nullptr, nullptr);
        attn_kernel<<<(N_M + 7) / 8, 256>>>(proj_tx, proj_m, rowptr0, srcs0, c1_p_rel, agg_m, N_M);
        attn_kernel<<<(N_TX + 7) / 8, 256>>>(proj_m, proj_tx, rowptr1, srcs1, c1_p_rel + 4, agg_tx, N_TX);
        // epilogue: h = relu( gelu(agg) @ Wa + ba )   (gelu fused into A staging)
        mma_gemm_kernel<1, 1><<<dim3(gbTX, 1), 256>>>(agg_tx, N_TX, 64, c1_Wa, 64, 0,
                                                      c1_ba, h_tx, 64, nullptr, nullptr);
        mma_gemm_kernel<1, 1><<<dim3(gbM, 1), 256>>>(agg_m, N_M, 64, c1_Wa + 4096, 64, 0,
                                                     c1_ba + 64, h_m, 64, nullptr, nullptr);
    }

    // ---- layer 2 (din = 64); only tx destination feeds the output ----
    {
        int din = 64;
        int effN = (din + 1) * 192;
        eff_weights_kernel<<<(effN + 255) / 256, 256>>>(
            c2_Wq, c2_bq, c2_Wk, c2_bk, c2_Wv, c2_bv, c2_a_rel, c2_m_rel, WA, bA, din);
        eff_weights_kernel<<<(effN + 255) / 256, 256>>>(
            c2_Wq + din * 64, c2_bq + 64, c2_Wk + din * 64, c2_bk + 64,
            c2_Wv + din * 64, c2_bv + 64, c2_a_rel + 1024, c2_m_rel + 1024, WB, bB, din);
        // tx needs only Q (cols 0..63); m needs only Khat/Vhat (cols 64..191)
        mma_gemm_kernel<0, 0><<<dim3(gbTX, 1), 256>>>(h_tx, N_TX, din, WA, 192, 0,
                                                      bA, proj_tx, 192, nullptr, nullptr);
        mma_gemm_kernel<0, 0><<<dim3(gbM, 2), 256>>>(h_m, N_M, din, WB, 192, 64,
                                                     bB, proj_m, 192, nullptr, nullptr);
        attn_kernel<<<(N_TX + 7) / 8, 256>>>(proj_m, proj_tx, rowptr1, srcs1, c2_p_rel + 4, agg_tx, N_TX);
        // skip-mix epilogue, in place on h_tx (same thread reads x_in then writes)
        mma_gemm_kernel<2, 1><<<dim3(gbTX, 1), 256>>>(agg_tx, N_TX, 64, c2_Wa, 64, 0,
                                                      c2_ba, h_tx, 64, h_tx, c2_skip);
    }

    final_kernel<<<(N_TX + 7) / 8, 256>>>(h_tx, Wc, bc, (float*)d_out, N_TX);
}

// round 7
// speedup vs baseline: 1.4037x; 1.0248x over previous
#include <cuda_runtime.h>
#include <cuda_bf16.h>
#include <cuda_fp16.h>
#include <cstdint>

#define NTX_MAX 100000
#define NM_MAX  20000
#define E_MAX   500000

// ---------------- scratch (static device globals; no runtime allocation) ----------------
__device__ float  g_q_tx [(size_t)NTX_MAX * 64];   // fp32 Q
__device__ float  g_q_m  [(size_t)NM_MAX  * 64];
__device__ __half g_kv_tx[(size_t)NTX_MAX * 128];  // fp16 [Khat | Vhat]
__device__ __half g_kv_m [(size_t)NM_MAX  * 128];
__device__ float  g_agg_tx[(size_t)NTX_MAX * 64];
__device__ float  g_agg_m [(size_t)NM_MAX  * 64];
__device__ float  g_h_tx  [(size_t)NTX_MAX * 64];
__device__ float  g_h_m   [(size_t)NM_MAX  * 64];
__device__ float  g_WA[128 * 192];   // effective fused QKV weights (fp32), type tx
__device__ float  g_bA[192];
__device__ float  g_WB[128 * 192];   // type m
__device__ float  g_bB[192];
// CSR
__device__ int g_rowptr0[NM_MAX + 1];   // dst = m   (tx->m edges)
__device__ int g_rowptr1[NTX_MAX + 1];  // dst = tx  (m->tx edges)
__device__ int g_cursor0[NM_MAX];
__device__ int g_cursor1[NTX_MAX];
__device__ int g_srcs0[E_MAX];
__device__ int g_srcs1[E_MAX];

// ---------------- CSR build ----------------
__global__ void zero_int_kernel(int* p, int n) {
    int i = blockIdx.x * blockDim.x + threadIdx.x;
    if (i < n) p[i] = 0;
}

__global__ void hist_kernel(const int* __restrict__ dst, int* __restrict__ cnt, int E) {
    int e = blockIdx.x * blockDim.x + threadIdx.x;
    if (e < E) atomicAdd(&cnt[dst[e]], 1);
}

// Single-block exclusive scan; writes rowptr[0..n] and cursor[i]=rowptr[i].
__global__ void scan_kernel(const int* __restrict__ cnt, int* __restrict__ rowptr,
                            int* __restrict__ cursor, int n) {
    __shared__ int ssum[1024];
    int tid = threadIdx.x;
    int chunk = (n + 1023) / 1024;
    int start = tid * chunk;
    int end = start + chunk; if (end > n) end = n; if (start > n) start = n;
    int s = 0;
    for (int i = start; i < end; i++) s += cnt[i];
    ssum[tid] = s;
    __syncthreads();
    for (int off = 1; off < 1024; off <<= 1) {
        int v = (tid >= off) ? ssum[tid - off] : 0;
        __syncthreads();
        ssum[tid] += v;
        __syncthreads();
    }
    int run = (tid == 0) ? 0 : ssum[tid - 1];
    for (int i = start; i < end; i++) {
        int c = cnt[i];
        rowptr[i] = run;
        cursor[i] = run;
        run += c;
    }
    if (tid == 1023) rowptr[n] = run;
}

__global__ void scatter_kernel(const int* __restrict__ src, const int* __restrict__ dst,
                               int* __restrict__ cursor, int* __restrict__ srcs_out, int E) {
    int e = blockIdx.x * blockDim.x + threadIdx.x;
    if (e < E) {
        int p = atomicAdd(&cursor[dst[e]], 1);
        srcs_out[p] = src[e];
    }
}

// ---------------- effective fused weights (fp32) ----------------
__global__ void eff_weights_kernel(const float* __restrict__ Wq, const float* __restrict__ bq,
                                   const float* __restrict__ Wk, const float* __restrict__ bk,
                                   const float* __restrict__ Wv, const float* __restrict__ bv,
                                   const float* __restrict__ a_rel, const float* __restrict__ m_rel,
                                   float* __restrict__ Wout, float* __restrict__ bout, int din) {
    int idx = blockIdx.x * blockDim.x + threadIdx.x;
    int total = (din + 1) * 192;
    if (idx >= total) return;
    int i = idx / 192, c = idx % 192;
    bool isBias = (i == din);
    float val;
    if (c < 64) {
        val = isBias ? bq[c] : Wq[i * 64 + c];
    } else {
        int cc = c - 64;
        bool isV = (cc >= 64);
        if (isV) cc -= 64;
        int h = cc >> 4, e = cc & 15;
        const float* rel  = isV ? m_rel : a_rel;
        const float* Wsrc = isV ? Wv : Wk;
        const float* bsrc = isV ? bv : bk;
        float s = 0.f;
        #pragma unroll
        for (int d = 0; d < 16; d++) {
            float w = isBias ? bsrc[h * 16 + d] : Wsrc[i * 64 + h * 16 + d];
            s += w * rel[h * 256 + d * 16 + e];
        }
        val = s;
    }
    if (isBias) bout[c] = val;
    else        Wout[i * 192 + c] = val;
}

// ---------------- tensor-core GEMM (fused fp32->bf16 3-split, fp32 accumulate) ----------------
__device__ __forceinline__ void ldsm_x4(uint32_t* r, uint32_t addr) {
    asm volatile("ldmatrix.sync.aligned.m8n8.x4.shared.b16 {%0,%1,%2,%3}, [%4];"
        : "=r"(r[0]), "=r"(r[1]), "=r"(r[2]), "=r"(r[3]) : "r"(addr));
}
__device__ __forceinline__ void ldsm_x4_t(uint32_t* r, uint32_t addr) {
    asm volatile("ldmatrix.sync.aligned.m8n8.x4.trans.shared.b16 {%0,%1,%2,%3}, [%4];"
        : "=r"(r[0]), "=r"(r[1]), "=r"(r[2]), "=r"(r[3]) : "r"(addr));
}
__device__ __forceinline__ void mma_bf16(float* c, const uint32_t* a, uint32_t b0, uint32_t b1) {
    asm volatile("mma.sync.aligned.m16n8k16.row.col.f32.bf16.bf16.f32 "
        "{%0,%1,%2,%3}, {%4,%5,%6,%7}, {%8,%9}, {%0,%1,%2,%3};"
        : "+f"(c[0]), "+f"(c[1]), "+f"(c[2]), "+f"(c[3])
        : "r"(a[0]), "r"(a[1]), "r"(a[2]), "r"(a[3]), "r"(b0), "r"(b1));
}

__device__ __forceinline__ void split2(float x, float y, uint32_t& hi, uint32_t& lo) {
    __nv_bfloat16 hx = __float2bfloat16_rn(x), hy = __float2bfloat16_rn(y);
    __nv_bfloat16 lx = __float2bfloat16_rn(x - __bfloat162float(hx));
    __nv_bfloat16 ly = __float2bfloat16_rn(y - __bfloat162float(hy));
    __nv_bfloat162 h2 = __halves2bfloat162(hx, hy);
    __nv_bfloat162 l2 = __halves2bfloat162(lx, ly);
    hi = *(uint32_t*)&h2;
    lo = *(uint32_t*)&l2;
}

__device__ __forceinline__ float gelu_exact(float v) {
    return 0.5f * v * (1.f + erff(v * 0.70710678118654752f));
}

#define AS_STRIDE 40   // 32 + 8 pad (bf16 elems): conflict-free ldmatrix
#define BS_STRIDE 72   // 64 + 8 pad

// POST: 0 = bias only, 1 = bias+relu, 2 = bias + skip-mix (a*o + (1-a)*x_in)
// AGELU: apply exact gelu to A elements while staging.
// Output: if outH != nullptr and this block's cols >= 64, write fp16 KV at col-64
// (ld 128); otherwise fp32 to outF (ld ldo).
template <int POST, int AGELU>
__global__ __launch_bounds__(256) void mma_gemm_kernel(
    const float* __restrict__ A, int N, int DIN,
    const float* __restrict__ B, int ldb, int col0,
    const float* __restrict__ bias,
    float* __restrict__ outF, int ldo, __half* __restrict__ outH,
    const float* __restrict__ x_in, const float* __restrict__ skipv) {
    __shared__ __nv_bfloat16 As[2][128 * AS_STRIDE];
    __shared__ __nv_bfloat16 Bs[2][32 * BS_STRIDE];

    int t = threadIdx.x;
    int w = t >> 5, lane = t & 31;
    int row0 = blockIdx.x * 128;
    int colW = col0 + blockIdx.y * 64;

    int mbase = (w >> 1) * 32;
    int nbase = (w & 1) * 32;
    int lrow = lane & 15;
    int lcolo = (lane >> 4) * 8;

    uint32_t a_base0 = (uint32_t)__cvta_generic_to_shared(&As[0][0]);
    uint32_t a_base1 = (uint32_t)__cvta_generic_to_shared(&As[1][0]);
    uint32_t b_base0 = (uint32_t)__cvta_generic_to_shared(&Bs[0][0]);
    uint32_t b_base1 = (uint32_t)__cvta_generic_to_shared(&Bs[1][0]);

    float acc[2][4][4];
    #pragma unroll
    for (int i = 0; i < 2; i++)
        #pragma unroll
        for (int j = 0; j < 4; j++)
            #pragma unroll
            for (int q = 0; q < 4; q++) acc[i][j][q] = 0.f;

    // A-row/B-row indices for this thread's staging slots
    int ar = t >> 1;                 // pattern per ii below
    (void)ar;

    float4 pa[4];
    float4 pb[2];

    // ---- prefetch chunk 0 ----
    #pragma unroll
    for (int ii = 0; ii < 4; ii++) {
        int idx = t + ii * 256;
        int r = idx >> 3, q = idx & 7;
        int grow = row0 + r;
        pa[ii] = make_float4(0.f, 0.f, 0.f, 0.f);
        if (grow < N) pa[ii] = *(const float4*)(A + (size_t)grow * DIN + 0 + q * 4);
    }
    #pragma unroll
    for (int ii = 0; ii < 2; ii++) {
        int idx = t + ii * 256;
        int r = idx >> 4, q = idx & 15;
        pb[ii] = *(const float4*)(B + (size_t)(0 + r) * ldb + colW + q * 4);
    }

    for (int k0 = 0; k0 < DIN; k0 += 32) {
        // ---- stage prefetched chunk into smem (with split + optional gelu) ----
        #pragma unroll
        for (int ii = 0; ii < 4; ii++) {
            int idx = t + ii * 256;
            int r = idx >> 3, q = idx & 7;
            float4 v = pa[ii];
            if (AGELU) {
                v.x = gelu_exact(v.x); v.y = gelu_exact(v.y);
                v.z = gelu_exact(v.z); v.w = gelu_exact(v.w);
            }
            uint32_t h0, l0, h1, l1;
            split2(v.x, v.y, h0, l0);
            split2(v.z, v.w, h1, l1);
            *(uint2*)(&As[0][r * AS_STRIDE + q * 4]) = make_uint2(h0, h1);
            *(uint2*)(&As[1][r * AS_STRIDE + q * 4]) = make_uint2(l0, l1);
        }
        #pragma unroll
        for (int ii = 0; ii < 2; ii++) {
            int idx = t + ii * 256;
            int r = idx >> 4, q = idx & 15;
            float4 v = pb[ii];
            uint32_t h0, l0, h1, l1;
            split2(v.x, v.y, h0, l0);
            split2(v.z, v.w, h1, l1);
            *(uint2*)(&Bs[0][r * BS_STRIDE + q * 4]) = make_uint2(h0, h1);
            *(uint2*)(&Bs[1][r * BS_STRIDE + q * 4]) = make_uint2(l0, l1);
        }
        __syncthreads();

        // ---- prefetch next chunk (overlaps with MMA below) ----
        int kn = k0 + 32;
        if (kn < DIN) {
            #pragma unroll
            for (int ii = 0; ii < 4; ii++) {
                int idx = t + ii * 256;
                int r = idx >> 3, q = idx & 7;
                int grow = row0 + r;
                pa[ii] = make_float4(0.f, 0.f, 0.f, 0.f);
                if (grow < N) pa[ii] = *(const float4*)(A + (size_t)grow * DIN + kn + q * 4);
            }
            #pragma unroll
            for (int ii = 0; ii < 2; ii++) {
                int idx = t + ii * 256;
                int r = idx >> 4, q = idx & 15;
                pb[ii] = *(const float4*)(B + (size_t)(kn + r) * ldb + colW + q * 4);
            }
        }

        #pragma unroll
        for (int kb = 0; kb < 32; kb += 16) {
            uint32_t ah[2][4], al[2][4], bh[2][4], bl[2][4];
            #pragma unroll
            for (int i = 0; i < 2; i++) {
                uint32_t off = (uint32_t)(((mbase + i * 16 + lrow) * AS_STRIDE + kb + lcolo) * 2);
                ldsm_x4(ah[i], a_base0 + off);
                ldsm_x4(al[i], a_base1 + off);
            }
            #pragma unroll
            for (int j2 = 0; j2 < 2; j2++) {
                uint32_t off = (uint32_t)(((kb + lrow) * BS_STRIDE + nbase + j2 * 16 + lcolo) * 2);
                ldsm_x4_t(bh[j2], b_base0 + off);
                ldsm_x4_t(bl[j2], b_base1 + off);
            }
            #pragma unroll
            for (int i = 0; i < 2; i++)
                #pragma unroll
                for (int j = 0; j < 4; j++) {
                    int j2 = j >> 1, o = (j & 1) * 2;
                    mma_bf16(acc[i][j], ah[i], bh[j2][o], bh[j2][o + 1]);
                    mma_bf16(acc[i][j], ah[i], bl[j2][o], bl[j2][o + 1]);
                    mma_bf16(acc[i][j], al[i], bh[j2][o], bh[j2][o + 1]);
                }
        }
        __syncthreads();
    }

    // epilogue
    int g = lane >> 2, tq = lane & 3;
    bool kvOut = (outH != nullptr) && (colW >= 64);
    float amix = 0.f;
    if (POST == 2) amix = 1.f / (1.f + __expf(-skipv[0]));
    #pragma unroll
    for (int i = 0; i < 2; i++) {
        #pragma unroll
        for (int j = 0; j < 4; j++) {
            int colg = colW + nbase + j * 8 + tq * 2;
            float b0 = bias[colg], b1 = bias[colg + 1];
            #pragma unroll
            for (int half = 0; half < 2; half++) {
                int row = row0 + mbase + i * 16 + g + half * 8;
                if (row < N) {
                    float o0 = acc[i][j][half * 2 + 0] + b0;
                    float o1 = acc[i][j][half * 2 + 1] + b1;
                    if (POST == 1) { o0 = fmaxf(o0, 0.f); o1 = fmaxf(o1, 0.f); }
                    if (POST == 2) {
                        o0 = amix * o0 + (1.f - amix) * x_in[(size_t)row * 64 + colg];
                        o1 = amix * o1 + (1.f - amix) * x_in[(size_t)row * 64 + colg + 1];
                    }
                    if (kvOut) {
                        __half2 hv = __floats2half2_rn(o0, o1);
                        *(__half2*)(outH + (size_t)row * 128 + (colg - 64)) = hv;
                    } else {
                        *(float2*)(outF + (size_t)row * ldo + colg) = make_float2(o0, o1);
                    }
                }
            }
        }
    }
}

// ---------------- attention: warp per dst, 8 lanes per edge, 4 edges in flight ----------------
// K/V in fp16 (kvS: [N][128] = [K|V]); Q fp32 (qD: [N][64]).
// lane = 8*eg + sub; sub owns channels [8*sub, 8*sub+8); head = sub>>1.
__global__ __launch_bounds__(256) void attn_kernel(
    const __half* __restrict__ kvS, const float* __restrict__ qD,
    const int* __restrict__ rowptr, const int* __restrict__ srcs,
    const float* __restrict__ p_rel, float* __restrict__ agg, int n_dst) {
    int w = threadIdx.x >> 5, lane = threadIdx.x & 31;
    int dst = blockIdx.x * 8 + w;
    if (dst >= n_dst) return;
    int sub = lane & 7;
    int eg = lane >> 3;
    const float* qd = qD + (size_t)dst * 64 + sub * 8;
    float4 q0 = *(const float4*)(qd);
    float4 q1 = *(const float4*)(qd + 4);
    float pr = p_rel[sub >> 1] * 0.25f;   // /SQRT_D folded
    float4 a0 = make_float4(0.f, 0.f, 0.f, 0.f);
    float4 a1 = make_float4(0.f, 0.f, 0.f, 0.f);
    float den = 0.f;
    int beg = rowptr[dst], end = rowptr[dst + 1];
    for (int i = beg; i < end; i += 4) {
        int ei = i + eg;
        bool valid = ei < end;
        int s = srcs[valid ? ei : beg];
        const __half* ps = kvS + (size_t)s * 128 + sub * 8;
        uint4 kraw = *(const uint4*)(ps);        // 8 halfs: K slice
        uint4 vraw = *(const uint4*)(ps + 64);   // 8 halfs: V slice
        float2 k0 = __half22float2(*(__half2*)&kraw.x);
        float2 k1 = __half22float2(*(__half2*)&kraw.y);
        float2 k2 = __half22float2(*(__half2*)&kraw.z);
        float2 k3 = __half22float2(*(__half2*)&kraw.w);
        float part = q0.x * k0.x + q0.y * k0.y + q0.z * k1.x + q0.w * k1.y
                   + q1.x * k2.x + q1.y * k2.y + q1.z * k3.x + q1.w * k3.y;
        part += __shfl_xor_sync(0xffffffffu, part, 1);
        float e = valid ? __expf(part * pr) : 0.f;
        float2 v0 = __half22float2(*(__half2*)&vraw.x);
        float2 v1 = __half22float2(*(__half2*)&vraw.y);
        float2 v2 = __half22float2(*(__half2*)&vraw.z);
        float2 v3 = __half22float2(*(__half2*)&vraw.w);
        a0.x = fmaf(e, v0.x, a0.x); a0.y = fmaf(e, v0.y, a0.y);
        a0.z = fmaf(e, v1.x, a0.z); a0.w = fmaf(e, v1.y, a0.w);
        a1.x = fmaf(e, v2.x, a1.x); a1.y = fmaf(e, v2.y, a1.y);
        a1.z = fmaf(e, v3.x, a1.z); a1.w = fmaf(e, v3.y, a1.w);
        den += e;
    }
    #pragma unroll
    for (int off = 8; off <= 16; off <<= 1) {
        a0.x += __shfl_xor_sync(0xffffffffu, a0.x, off);
        a0.y += __shfl_xor_sync(0xffffffffu, a0.y, off);
        a0.z += __shfl_xor_sync(0xffffffffu, a0.z, off);
        a0.w += __shfl_xor_sync(0xffffffffu, a0.w, off);
        a1.x += __shfl_xor_sync(0xffffffffu, a1.x, off);
        a1.y += __shfl_xor_sync(0xffffffffu, a1.y, off);
        a1.z += __shfl_xor_sync(0xffffffffu, a1.z, off);
        a1.w += __shfl_xor_sync(0xffffffffu, a1.w, off);
        den  += __shfl_xor_sync(0xffffffffu, den, off);
    }
    if (lane < 8) {
        float inv = 1.f / (den + 1e-16f);
        a0.x *= inv; a0.y *= inv; a0.z *= inv; a0.w *= inv;
        a1.x *= inv; a1.y *= inv; a1.z *= inv; a1.w *= inv;
        float* op = agg + (size_t)dst * 64 + sub * 8;
        *(float4*)(op) = a0;
        *(float4*)(op + 4) = a1;
    }
}

// ---------------- final logits ----------------
__global__ __launch_bounds__(256) void final_kernel(
    const float* __restrict__ h, const float* __restrict__ Wc, const float* __restrict__ bc,
    float* __restrict__ out, int N) {
    int warp = (blockIdx.x * blockDim.x + threadIdx.x) >> 5;
    int lane = threadIdx.x & 31;
    if (warp >= N) return;
    float s = h[(size_t)warp * 64 + lane] * Wc[lane] + h[(size_t)warp * 64 + 32 + lane] * Wc[32 + lane];
    #pragma unroll
    for (int off = 16; off; off >>= 1) s += __shfl_xor_sync(0xffffffffu, s, off);
    if (lane == 0) out[warp] = s + bc[0];
}

// ---------------- launch ----------------
extern "C" void kernel_launch(void* const* d_in, const int* in_sizes, int n_in,
                              void* d_out, int out_size) {
    (void)n_in; (void)out_size;
    int ebase, wbase;
    if (in_sizes[2] > 100000) { ebase = 2;  wbase = 6; }
    else                      { ebase = 27; wbase = 2; }

    const float* x_tx = (const float*)d_in[0];
    const float* x_m  = (const float*)d_in[1];
    const int* tm_src = (const int*)d_in[ebase + 0];
    const int* tm_dst = (const int*)d_in[ebase + 1];
    const int* mt_src = (const int*)d_in[ebase + 2];
    const int* mt_dst = (const int*)d_in[ebase + 3];

    const float* c1_Wk    = (const float*)d_in[wbase + 0];
    const float* c1_bk    = (const float*)d_in[wbase + 1];
    const float* c1_Wq    = (const float*)d_in[wbase + 2];
    const float* c1_bq    = (const float*)d_in[wbase + 3];
    const float* c1_Wv    = (const float*)d_in[wbase + 4];
    const float* c1_bv    = (const float*)d_in[wbase + 5];
    const float* c1_a_rel = (const float*)d_in[wbase + 6];
    const float* c1_m_rel = (const float*)d_in[wbase + 7];
    const float* c1_p_rel = (const float*)d_in[wbase + 8];
    const float* c1_Wa    = (const float*)d_in[wbase + 9];
    const float* c1_ba    = (const float*)d_in[wbase + 10];
    const float* c2_Wk    = (const float*)d_in[wbase + 11];
    const float* c2_bk    = (const float*)d_in[wbase + 12];
    const float* c2_Wq    = (const float*)d_in[wbase + 13];
    const float* c2_bq    = (const float*)d_in[wbase + 14];
    const float* c2_Wv    = (const float*)d_in[wbase + 15];
    const float* c2_bv    = (const float*)d_in[wbase + 16];
    const float* c2_a_rel = (const float*)d_in[wbase + 17];
    const float* c2_m_rel = (const float*)d_in[wbase + 18];
    const float* c2_p_rel = (const float*)d_in[wbase + 19];
    const float* c2_Wa    = (const float*)d_in[wbase + 20];
    const float* c2_ba    = (const float*)d_in[wbase + 21];
    const float* c2_skip  = (const float*)d_in[wbase + 22];
    const float* Wc       = (const float*)d_in[wbase + 23];
    const float* bc       = (const float*)d_in[wbase + 24];

    int N_TX = in_sizes[0] / 128;
    int N_M  = in_sizes[1] / 128;
    int E0 = in_sizes[ebase + 1];
    int E1 = in_sizes[ebase + 3];

    void* p;
    float *q_tx, *q_m, *agg_tx, *agg_m, *h_tx, *h_m, *WA, *bA, *WB, *bB;
    __half *kv_tx, *kv_m;
    int *rowptr0, *rowptr1, *cursor0, *cursor1, *srcs0, *srcs1;
    cudaGetSymbolAddress(&p, g_q_tx);    q_tx    = (float*)p;
    cudaGetSymbolAddress(&p, g_q_m);     q_m     = (float*)p;
    cudaGetSymbolAddress(&p, g_kv_tx);   kv_tx   = (__half*)p;
    cudaGetSymbolAddress(&p, g_kv_m);    kv_m    = (__half*)p;
    cudaGetSymbolAddress(&p, g_agg_tx);  agg_tx  = (float*)p;
    cudaGetSymbolAddress(&p, g_agg_m);   agg_m   = (float*)p;
    cudaGetSymbolAddress(&p, g_h_tx);    h_tx    = (float*)p;
    cudaGetSymbolAddress(&p, g_h_m);     h_m     = (float*)p;
    cudaGetSymbolAddress(&p, g_WA);      WA      = (float*)p;
    cudaGetSymbolAddress(&p, g_bA);      bA      = (float*)p;
    cudaGetSymbolAddress(&p, g_WB);      WB      = (float*)p;
    cudaGetSymbolAddress(&p, g_bB);      bB      = (float*)p;
    cudaGetSymbolAddress(&p, g_rowptr0); rowptr0 = (int*)p;
    cudaGetSymbolAddress(&p, g_rowptr1); rowptr1 = (int*)p;
    cudaGetSymbolAddress(&p, g_cursor0); cursor0 = (int*)p;
    cudaGetSymbolAddress(&p, g_cursor1); cursor1 = (int*)p;
    cudaGetSymbolAddress(&p, g_srcs0);   srcs0   = (int*)p;
    cudaGetSymbolAddress(&p, g_srcs1);   srcs1   = (int*)p;

    int gbTX = (N_TX + 127) / 128;
    int gbM  = (N_M + 127) / 128;

    // ---- CSR build ----
    zero_int_kernel<<<(N_M + 255) / 256, 256>>>(cursor0, N_M);
    zero_int_kernel<<<(N_TX + 255) / 256, 256>>>(cursor1, N_TX);
    hist_kernel<<<(E0 + 255) / 256, 256>>>(tm_dst, cursor0, E0);
    hist_kernel<<<(E1 + 255) / 256, 256>>>(mt_dst, cursor1, E1);
    scan_kernel<<<1, 1024>>>(cursor0, rowptr0, cursor0, N_M);
    scan_kernel<<<1, 1024>>>(cursor1, rowptr1, cursor1, N_TX);
    scatter_kernel<<<(E0 + 255) / 256, 256>>>(tm_src, tm_dst, cursor0, srcs0, E0);
    scatter_kernel<<<(E1 + 255) / 256, 256>>>(mt_src, mt_dst, cursor1, srcs1, E1);

    // ---- layer 1 (din = 128) ----
    {
        int din = 128;
        int effN = (din + 1) * 192;
        eff_weights_kernel<<<(effN + 255) / 256, 256>>>(
            c1_Wq, c1_bq, c1_Wk, c1_bk, c1_Wv, c1_bv, c1_a_rel, c1_m_rel, WA, bA, din);
        eff_weights_kernel<<<(effN + 255) / 256, 256>>>(
            c1_Wq + din * 64, c1_bq + 64, c1_Wk + din * 64, c1_bk + 64,
            c1_Wv + din * 64, c1_bv + 64, c1_a_rel + 1024, c1_m_rel + 1024, WB, bB, din);
        mma_gemm_kernel<0, 0><<<dim3(gbTX, 3), 256>>>(x_tx, N_TX, din, WA, 192, 0,
                                                      bA, q_tx, 64, kv_tx, nullptr, nullptr);
        mma_gemm_kernel<0, 0><<<dim3(gbM, 3), 256>>>(x_m, N_M, din, WB, 192, 0,
                                                     bB, q_m, 64, kv_m, nullptr, nullptr);
        attn_kernel<<<(N_M + 7) / 8, 256>>>(kv_tx, q_m, rowptr0, srcs0, c1_p_rel, agg_m, N_M);
        attn_kernel<<<(N_TX + 7) / 8, 256>>>(kv_m, q_tx, rowptr1, srcs1, c1_p_rel + 4, agg_tx, N_TX);
        // epilogue: h = relu( gelu(agg) @ Wa + ba )
        mma_gemm_kernel<1, 1><<<dim3(gbTX, 1), 256>>>(agg_tx, N_TX, 64, c1_Wa, 64, 0,
                                                      c1_ba, h_tx, 64, nullptr, nullptr, nullptr);
        mma_gemm_kernel<1, 1><<<dim3(gbM, 1), 256>>>(agg_m, N_M, 64, c1_Wa + 4096, 64, 0,
                                                     c1_ba + 64, h_m, 64, nullptr, nullptr, nullptr);
    }

    // ---- layer 2 (din = 64); only tx destination feeds the output ----
    {
        int din = 64;
        int effN = (din + 1) * 192;
        eff_weights_kernel<<<(effN + 255) / 256, 256>>>(
            c2_Wq, c2_bq, c2_Wk, c2_bk, c2_Wv, c2_bv, c2_a_rel, c2_m_rel, WA, bA, din);
        eff_weights_kernel<<<(effN + 255) / 256, 256>>>(
            c2_Wq + din * 64, c2_bq + 64, c2_Wk + din * 64, c2_bk + 64,
            c2_Wv + din * 64, c2_bv + 64, c2_a_rel + 1024, c2_m_rel + 1024, WB, bB, din);
        // tx needs only Q (cols 0..63); m needs only Khat/Vhat (cols 64..191)
        mma_gemm_kernel<0, 0><<<dim3(gbTX, 1), 256>>>(h_tx, N_TX, din, WA, 192, 0,
                                                      bA, q_tx, 64, nullptr, nullptr, nullptr);
        mma_gemm_kernel<0, 0><<<dim3(gbM, 2), 256>>>(h_m, N_M, din, WB, 192, 64,
                                                     bB, nullptr, 0, kv_m, nullptr, nullptr);
        attn_kernel<<<(N_TX + 7) / 8, 256>>>(kv_m, q_tx, rowptr1, srcs1, c2_p_rel + 4, agg_tx, N_TX);
        // skip-mix epilogue, in place on h_tx (same thread reads x_in then writes)
        mma_gemm_kernel<2, 1><<<dim3(gbTX, 1), 256>>>(agg_tx, N_TX, 64, c2_Wa, 64, 0,
                                                      c2_ba, h_tx, 64, nullptr, h_tx, c2_skip);
    }

    final_kernel<<<(N_TX + 7) / 8, 256>>>(h_tx, Wc, bc, (float*)d_out, N_TX);
}

// round 8
// speedup vs baseline: 1.5708x; 1.1191x over previous
#include <cuda_runtime.h>
#include <cuda_bf16.h>
#include <cuda_fp16.h>
#include <cstdint>

#define NTX_MAX 100000
#define NM_MAX  20000
#define E_MAX   500000

// ---------------- scratch (static device globals; no runtime allocation) ----------------
__device__ float  g_q_tx [(size_t)NTX_MAX * 64];   // fp32 Q
__device__ float  g_q_m  [(size_t)NM_MAX  * 64];
__device__ __half g_kv_tx[(size_t)NTX_MAX * 128];  // fp16 [Khat | Vhat]
__device__ __half g_kv_m [(size_t)NM_MAX  * 128];
__device__ float  g_agg_tx[(size_t)NTX_MAX * 64];
__device__ float  g_agg_m [(size_t)NM_MAX  * 64];
__device__ float  g_h_tx  [(size_t)NTX_MAX * 64];
__device__ float  g_h_m   [(size_t)NM_MAX  * 64];
__device__ float  g_WA1[128 * 192];  __device__ float g_bA1[192];
__device__ float  g_WB1[128 * 192];  __device__ float g_bB1[192];
__device__ float  g_WA2[128 * 192];  __device__ float g_bA2[192];
__device__ float  g_WB2[128 * 192];  __device__ float g_bB2[192];
// CSR
__device__ int g_rowptr0[NM_MAX + 1];   // dst = m   (tx->m edges)
__device__ int g_rowptr1[NTX_MAX + 1];  // dst = tx  (m->tx edges)
__device__ int g_cursor0[NM_MAX];
__device__ int g_cursor1[NTX_MAX];
__device__ int g_srcs0[E_MAX];
__device__ int g_srcs1[E_MAX];

// ---------------- CSR build (merged over both graphs) ----------------
__global__ void zero_both_kernel(int* p0, int n0, int* p1, int n1) {
    int i = blockIdx.x * blockDim.x + threadIdx.x;
    if (i < n0) p0[i] = 0;
    else if (i < n0 + n1) p1[i - n0] = 0;
}

__global__ void hist_both_kernel(const int* __restrict__ d0, int E0, int* __restrict__ c0,
                                 const int* __restrict__ d1, int E1, int* __restrict__ c1) {
    int e = blockIdx.x * blockDim.x + threadIdx.x;
    if (e < E0) atomicAdd(&c0[d0[e]], 1);
    else if (e < E0 + E1) atomicAdd(&c1[d1[e - E0]], 1);
}

// two blocks: block 0 -> graph0, block 1 -> graph1
__global__ void scan_both_kernel(int* __restrict__ cnt0, int* __restrict__ rp0, int n0,
                                 int* __restrict__ cnt1, int* __restrict__ rp1, int n1) {
    __shared__ int ssum[1024];
    int* cnt = blockIdx.x ? cnt1 : cnt0;
    int* rowptr = blockIdx.x ? rp1 : rp0;
    int n = blockIdx.x ? n1 : n0;
    int tid = threadIdx.x;
    int chunk = (n + 1023) / 1024;
    int start = tid * chunk;
    int end = start + chunk; if (end > n) end = n; if (start > n) start = n;
    int s = 0;
    for (int i = start; i < end; i++) s += cnt[i];
    ssum[tid] = s;
    __syncthreads();
    for (int off = 1; off < 1024; off <<= 1) {
        int v = (tid >= off) ? ssum[tid - off] : 0;
        __syncthreads();
        ssum[tid] += v;
        __syncthreads();
    }
    int run = (tid == 0) ? 0 : ssum[tid - 1];
    for (int i = start; i < end; i++) {
        int c = cnt[i];
        rowptr[i] = run;
        cnt[i] = run;       // cursor = rowptr (cnt doubles as cursor)
        run += c;
    }
    if (tid == 1023) rowptr[n] = run;
}

__global__ void scatter_both_kernel(const int* __restrict__ s0, const int* __restrict__ d0, int E0,
                                    int* __restrict__ cur0, int* __restrict__ out0,
                                    const int* __restrict__ s1, const int* __restrict__ d1, int E1,
                                    int* __restrict__ cur1, int* __restrict__ out1) {
    int e = blockIdx.x * blockDim.x + threadIdx.x;
    if (e < E0) {
        int p = atomicAdd(&cur0[d0[e]], 1);
        out0[p] = s0[e];
    } else if (e < E0 + E1) {
        int ee = e - E0;
        int p = atomicAdd(&cur1[d1[ee]], 1);
        out1[p] = s1[ee];
    }
}

// ---------------- effective fused weights: all 4 (layer x type) in one launch ----------------
// y = blockIdx.y: 0 = L1 tx, 1 = L1 m, 2 = L2 tx, 3 = L2 m
__global__ void eff_all_kernel(
    const float* c1_Wq, const float* c1_bq, const float* c1_Wk, const float* c1_bk,
    const float* c1_Wv, const float* c1_bv, const float* c1_a, const float* c1_m,
    const float* c2_Wq, const float* c2_bq, const float* c2_Wk, const float* c2_bk,
    const float* c2_Wv, const float* c2_bv, const float* c2_a, const float* c2_m,
    float* WA1, float* bA1, float* WB1, float* bB1,
    float* WA2, float* bA2, float* WB2, float* bB2) {
    int y = blockIdx.y;
    int layer = y >> 1, typ = y & 1;
    int din = layer ? 64 : 128;
    int idx = blockIdx.x * blockDim.x + threadIdx.x;
    int total = (din + 1) * 192;
    if (idx >= total) return;
    const float* Wq = layer ? c2_Wq : c1_Wq;  const float* bq = layer ? c2_bq : c1_bq;
    const float* Wk = layer ? c2_Wk : c1_Wk;  const float* bk = layer ? c2_bk : c1_bk;
    const float* Wv = layer ? c2_Wv : c1_Wv;  const float* bv = layer ? c2_bv : c1_bv;
    const float* ar = layer ? c2_a : c1_a;    const float* mr = layer ? c2_m : c1_m;
    Wq += (size_t)typ * din * 64; bq += typ * 64;
    Wk += (size_t)typ * din * 64; bk += typ * 64;
    Wv += (size_t)typ * din * 64; bv += typ * 64;
    ar += typ * 1024; mr += typ * 1024;
    float* Wout = layer ? (typ ? WB2 : WA2) : (typ ? WB1 : WA1);
    float* bout = layer ? (typ ? bB2 : bA2) : (typ ? bB1 : bA1);

    int i = idx / 192, c = idx % 192;
    bool isBias = (i == din);
    float val;
    if (c < 64) {
        val = isBias ? bq[c] : Wq[i * 64 + c];
    } else {
        int cc = c - 64;
        bool isV = (cc >= 64);
        if (isV) cc -= 64;
        int h = cc >> 4, e = cc & 15;
        const float* rel  = isV ? mr : ar;
        const float* Wsrc = isV ? Wv : Wk;
        const float* bsrc = isV ? bv : bk;
        float s = 0.f;
        #pragma unroll
        for (int d = 0; d < 16; d++) {
            float w = isBias ? bsrc[h * 16 + d] : Wsrc[i * 64 + h * 16 + d];
            s += w * rel[h * 256 + d * 16 + e];
        }
        val = s;
    }
    if (isBias) bout[c] = val;
    else        Wout[i * 192 + c] = val;
}

// ---------------- tensor-core GEMM (fused fp32->bf16 3-split, fp32 accumulate) ----------------
__device__ __forceinline__ void ldsm_x4(uint32_t* r, uint32_t addr) {
    asm volatile("ldmatrix.sync.aligned.m8n8.x4.shared.b16 {%0,%1,%2,%3}, [%4];"
        : "=r"(r[0]), "=r"(r[1]), "=r"(r[2]), "=r"(r[3]) : "r"(addr));
}
__device__ __forceinline__ void ldsm_x4_t(uint32_t* r, uint32_t addr) {
    asm volatile("ldmatrix.sync.aligned.m8n8.x4.trans.shared.b16 {%0,%1,%2,%3}, [%4];"
        : "=r"(r[0]), "=r"(r[1]), "=r"(r[2]), "=r"(r[3]) : "r"(addr));
}
__device__ __forceinline__ void mma_bf16(float* c, const uint32_t* a, uint32_t b0, uint32_t b1) {
    asm volatile("mma.sync.aligned.m16n8k16.row.col.f32.bf16.bf16.f32 "
        "{%0,%1,%2,%3}, {%4,%5,%6,%7}, {%8,%9}, {%0,%1,%2,%3};"
        : "+f"(c[0]), "+f"(c[1]), "+f"(c[2]), "+f"(c[3])
        : "r"(a[0]), "r"(a[1]), "r"(a[2]), "r"(a[3]), "r"(b0), "r"(b1));
}

__device__ __forceinline__ void split2(float x, float y, uint32_t& hi, uint32_t& lo) {
    __nv_bfloat16 hx = __float2bfloat16_rn(x), hy = __float2bfloat16_rn(y);
    __nv_bfloat16 lx = __float2bfloat16_rn(x - __bfloat162float(hx));
    __nv_bfloat16 ly = __float2bfloat16_rn(y - __bfloat162float(hy));
    __nv_bfloat162 h2 = __halves2bfloat162(hx, hy);
    __nv_bfloat162 l2 = __halves2bfloat162(lx, ly);
    hi = *(uint32_t*)&h2;
    lo = *(uint32_t*)&l2;
}

__device__ __forceinline__ float gelu_exact(float v) {
    return 0.5f * v * (1.f + erff(v * 0.70710678118654752f));
}

#define AS_STRIDE 40   // 32 + 8 pad (bf16 elems): conflict-free ldmatrix

struct GemmJob {
    const float* A; const float* B; const float* bias; const float* x_in;
    float* outF; __half* outH;
    int N, ldb, col0, ldo, colBlocks;
};

// POST: 0 = bias only, 1 = bias+relu, 2 = bias + skip-mix.  AGELU: gelu(A) while staging.
// NCOLS: output columns per block (96 for QKV, 64 otherwise). 128 rows per block, 8 warps.
// fp16 KV epilogue: any colg >= 64 with outH set goes to outH (ld 128, offset -64).
template <int POST, int AGELU, int NCOLS>
__global__ __launch_bounds__(256) void mma_gemm_kernel(
    GemmJob j0, GemmJob j1, int nb0, int DIN, const float* __restrict__ skipv) {
    constexpr int NH = NCOLS / 2;        // warp n-width
    constexpr int J2N = NH / 16;         // ldsm_t groups per warp
    constexpr int JN = NH / 8;           // mma-n groups per warp
    constexpr int BSTR = NCOLS + 8;
    constexpr int BQ = NCOLS / 4;        // float4 per B row
    __shared__ __nv_bfloat16 As[2][128 * AS_STRIDE];
    __shared__ __nv_bfloat16 Bs[2][32 * BSTR];

    int bx = blockIdx.x;
    bool second = bx >= nb0;
    GemmJob J = second ? j1 : j0;
    int b = second ? bx - nb0 : bx;
    int rb, cb;
    if (J.colBlocks == 2) { rb = b >> 1; cb = b & 1; } else { rb = b; cb = 0; }
    int row0 = rb * 128;
    int colW = J.col0 + cb * NCOLS;

    int t = threadIdx.x;
    int w = t >> 5, lane = t & 31;
    int mbase = (w >> 1) * 32;
    int nbase = (w & 1) * NH;
    int lrow = lane & 15;
    int lcolo = (lane >> 4) * 8;

    uint32_t a_base0 = (uint32_t)__cvta_generic_to_shared(&As[0][0]);
    uint32_t a_base1 = (uint32_t)__cvta_generic_to_shared(&As[1][0]);
    uint32_t b_base0 = (uint32_t)__cvta_generic_to_shared(&Bs[0][0]);
    uint32_t b_base1 = (uint32_t)__cvta_generic_to_shared(&Bs[1][0]);

    float acc[2][JN][4];
    #pragma unroll
    for (int i = 0; i < 2; i++)
        #pragma unroll
        for (int j = 0; j < JN; j++)
            #pragma unroll
            for (int q = 0; q < 4; q++) acc[i][j][q] = 0.f;

    for (int k0 = 0; k0 < DIN; k0 += 32) {
        // stage A: 128 rows x 32 cols fp32 -> hi/lo bf16 (optional gelu)
        #pragma unroll
        for (int ii = 0; ii < 4; ii++) {
            int idx = t + ii * 256;          // 0..1023
            int r = idx >> 3, q = idx & 7;
            int grow = row0 + r;
            float4 v = make_float4(0.f, 0.f, 0.f, 0.f);
            if (grow < J.N) v = *(const float4*)(J.A + (size_t)grow * DIN + k0 + q * 4);
            if (AGELU) {
                v.x = gelu_exact(v.x); v.y = gelu_exact(v.y);
                v.z = gelu_exact(v.z); v.w = gelu_exact(v.w);
            }
            uint32_t h0, l0, h1, l1;
            split2(v.x, v.y, h0, l0);
            split2(v.z, v.w, h1, l1);
            *(uint2*)(&As[0][r * AS_STRIDE + q * 4]) = make_uint2(h0, h1);
            *(uint2*)(&As[1][r * AS_STRIDE + q * 4]) = make_uint2(l0, l1);
        }
        // stage B: 32 rows x NCOLS cols fp32 -> hi/lo bf16
        #pragma unroll
        for (int ii = 0; ii < NCOLS / 32; ii++) {
            int idx = t + ii * 256;           // 0 .. 32*BQ-1
            int r = idx / BQ, q = idx % BQ;
            float4 v = *(const float4*)(J.B + (size_t)(k0 + r) * J.ldb + colW + q * 4);
            uint32_t h0, l0, h1, l1;
            split2(v.x, v.y, h0, l0);
            split2(v.z, v.w, h1, l1);
            *(uint2*)(&Bs[0][r * BSTR + q * 4]) = make_uint2(h0, h1);
            *(uint2*)(&Bs[1][r * BSTR + q * 4]) = make_uint2(l0, l1);
        }
        __syncthreads();

        #pragma unroll
        for (int kb = 0; kb < 32; kb += 16) {
            uint32_t ah[2][4], al[2][4];
            #pragma unroll
            for (int i = 0; i < 2; i++) {
                uint32_t off = (uint32_t)(((mbase + i * 16 + lrow) * AS_STRIDE + kb + lcolo) * 2);
                ldsm_x4(ah[i], a_base0 + off);
                ldsm_x4(al[i], a_base1 + off);
            }
            #pragma unroll
            for (int j2 = 0; j2 < J2N; j2++) {
                uint32_t bh[4], bl[4];
                uint32_t off = (uint32_t)(((kb + lrow) * BSTR + nbase + j2 * 16 + lcolo) * 2);
                ldsm_x4_t(bh, b_base0 + off);
                ldsm_x4_t(bl, b_base1 + off);
                #pragma unroll
                for (int i = 0; i < 2; i++)
                    #pragma unroll
                    for (int jj = 0; jj < 2; jj++) {
                        int j = j2 * 2 + jj, o = jj * 2;
                        mma_bf16(acc[i][j], ah[i], bh[o], bh[o + 1]);
                        mma_bf16(acc[i][j], ah[i], bl[o], bl[o + 1]);
                        mma_bf16(acc[i][j], al[i], bh[o], bh[o + 1]);
                    }
            }
        }
        __syncthreads();
    }

    // epilogue
    int g = lane >> 2, tq = lane & 3;
    float amix = 0.f;
    if (POST == 2) amix = 1.f / (1.f + __expf(-skipv[0]));
    #pragma unroll
    for (int i = 0; i < 2; i++) {
        #pragma unroll
        for (int j = 0; j < JN; j++) {
            int colg = colW + nbase + j * 8 + tq * 2;
            float b0 = J.bias[colg], b1 = J.bias[colg + 1];
            #pragma unroll
            for (int half = 0; half < 2; half++) {
                int row = row0 + mbase + i * 16 + g + half * 8;
                if (row < J.N) {
                    float o0 = acc[i][j][half * 2 + 0] + b0;
                    float o1 = acc[i][j][half * 2 + 1] + b1;
                    if (POST == 1) { o0 = fmaxf(o0, 0.f); o1 = fmaxf(o1, 0.f); }
                    if (POST == 2) {
                        o0 = amix * o0 + (1.f - amix) * J.x_in[(size_t)row * 64 + colg];
                        o1 = amix * o1 + (1.f - amix) * J.x_in[(size_t)row * 64 + colg + 1];
                    }
                    if (J.outH != nullptr && colg >= 64) {
                        __half2 hv = __floats2half2_rn(o0, o1);
                        *(__half2*)(J.outH + (size_t)row * 128 + (colg - 64)) = hv;
                    } else {
                        *(float2*)(J.outF + (size_t)row * J.ldo + colg) = make_float2(o0, o1);
                    }
                }
            }
        }
    }
}

// ---------------- attention (merged over both dst sets) ----------------
struct AttnSet {
    const __half* kv; const float* q;
    const int* rp; const int* srcs;
    const float* prel; float* agg; int n;
};

__global__ __launch_bounds__(256) void attn_kernel(AttnSet s0, AttnSet s1) {
    int w = threadIdx.x >> 5, lane = threadIdx.x & 31;
    int d = blockIdx.x * 8 + w;
    AttnSet S;
    int dst;
    if (d < s0.n) { S = s0; dst = d; }
    else {
        dst = d - s0.n;
        if (dst >= s1.n) return;
        S = s1;
    }
    int sub = lane & 7;
    int eg = lane >> 3;
    const float* qd = S.q + (size_t)dst * 64 + sub * 8;
    float4 q0 = *(const float4*)(qd);
    float4 q1 = *(const float4*)(qd + 4);
    float pr = S.prel[sub >> 1] * 0.25f;   // /SQRT_D folded
    float4 a0 = make_float4(0.f, 0.f, 0.f, 0.f);
    float4 a1 = make_float4(0.f, 0.f, 0.f, 0.f);
    float den = 0.f;
    int beg = S.rp[dst], end = S.rp[dst + 1];
    for (int i = beg; i < end; i += 4) {
        int ei = i + eg;
        bool valid = ei < end;
        int s = S.srcs[valid ? ei : beg];
        const __half* ps = S.kv + (size_t)s * 128 + sub * 8;
        uint4 kraw = *(const uint4*)(ps);        // 8 halfs: K slice
        uint4 vraw = *(const uint4*)(ps + 64);   // 8 halfs: V slice
        float2 k0 = __half22float2(*(__half2*)&kraw.x);
        float2 k1 = __half22float2(*(__half2*)&kraw.y);
        float2 k2 = __half22float2(*(__half2*)&kraw.z);
        float2 k3 = __half22float2(*(__half2*)&kraw.w);
        float part = q0.x * k0.x + q0.y * k0.y + q0.z * k1.x + q0.w * k1.y
                   + q1.x * k2.x + q1.y * k2.y + q1.z * k3.x + q1.w * k3.y;
        part += __shfl_xor_sync(0xffffffffu, part, 1);
        float e = valid ? __expf(part * pr) : 0.f;
        float2 v0 = __half22float2(*(__half2*)&vraw.x);
        float2 v1 = __half22float2(*(__half2*)&vraw.y);
        float2 v2 = __half22float2(*(__half2*)&vraw.z);
        float2 v3 = __half22float2(*(__half2*)&vraw.w);
        a0.x = fmaf(e, v0.x, a0.x); a0.y = fmaf(e, v0.y, a0.y);
        a0.z = fmaf(e, v1.x, a0.z); a0.w = fmaf(e, v1.y, a0.w);
        a1.x = fmaf(e, v2.x, a1.x); a1.y = fmaf(e, v2.y, a1.y);
        a1.z = fmaf(e, v3.x, a1.z); a1.w = fmaf(e, v3.y, a1.w);
        den += e;
    }
    #pragma unroll
    for (int off = 8; off <= 16; off <<= 1) {
        a0.x += __shfl_xor_sync(0xffffffffu, a0.x, off);
        a0.y += __shfl_xor_sync(0xffffffffu, a0.y, off);
        a0.z += __shfl_xor_sync(0xffffffffu, a0.z, off);
        a0.w += __shfl_xor_sync(0xffffffffu, a0.w, off);
        a1.x += __shfl_xor_sync(0xffffffffu, a1.x, off);
        a1.y += __shfl_xor_sync(0xffffffffu, a1.y, off);
        a1.z += __shfl_xor_sync(0xffffffffu, a1.z, off);
        a1.w += __shfl_xor_sync(0xffffffffu, a1.w, off);
        den  += __shfl_xor_sync(0xffffffffu, den, off);
    }
    if (lane < 8) {
        float inv = 1.f / (den + 1e-16f);
        a0.x *= inv; a0.y *= inv; a0.z *= inv; a0.w *= inv;
        a1.x *= inv; a1.y *= inv; a1.z *= inv; a1.w *= inv;
        float* op = S.agg + (size_t)dst * 64 + sub * 8;
        *(float4*)(op) = a0;
        *(float4*)(op + 4) = a1;
    }
}

// ---------------- final logits ----------------
__global__ __launch_bounds__(256) void final_kernel(
    const float* __restrict__ h, const float* __restrict__ Wc, const float* __restrict__ bc,
    float* __restrict__ out, int N) {
    int warp = (blockIdx.x * blockDim.x + threadIdx.x) >> 5;
    int lane = threadIdx.x & 31;
    if (warp >= N) return;
    float s = h[(size_t)warp * 64 + lane] * Wc[lane] + h[(size_t)warp * 64 + 32 + lane] * Wc[32 + lane];
    #pragma unroll
    for (int off = 16; off; off >>= 1) s += __shfl_xor_sync(0xffffffffu, s, off);
    if (lane == 0) out[warp] = s + bc[0];
}

// ---------------- launch ----------------
extern "C" void kernel_launch(void* const* d_in, const int* in_sizes, int n_in,
                              void* d_out, int out_size) {
    (void)n_in; (void)out_size;
    int ebase, wbase;
    if (in_sizes[2] > 100000) { ebase = 2;  wbase = 6; }
    else                      { ebase = 27; wbase = 2; }

    const float* x_tx = (const float*)d_in[0];
    const float* x_m  = (const float*)d_in[1];
    const int* tm_src = (const int*)d_in[ebase + 0];
    const int* tm_dst = (const int*)d_in[ebase + 1];
    const int* mt_src = (const int*)d_in[ebase + 2];
    const int* mt_dst = (const int*)d_in[ebase + 3];

    const float* c1_Wk    = (const float*)d_in[wbase + 0];
    const float* c1_bk    = (const float*)d_in[wbase + 1];
    const float* c1_Wq    = (const float*)d_in[wbase + 2];
    const float* c1_bq    = (const float*)d_in[wbase + 3];
    const float* c1_Wv    = (const float*)d_in[wbase + 4];
    const float* c1_bv    = (const float*)d_in[wbase + 5];
    const float* c1_a_rel = (const float*)d_in[wbase + 6];
    const float* c1_m_rel = (const float*)d_in[wbase + 7];
    const float* c1_p_rel = (const float*)d_in[wbase + 8];
    const float* c1_Wa    = (const float*)d_in[wbase + 9];
    const float* c1_ba    = (const float*)d_in[wbase + 10];
    const float* c2_Wk    = (const float*)d_in[wbase + 11];
    const float* c2_bk    = (const float*)d_in[wbase + 12];
    const float* c2_Wq    = (const float*)d_in[wbase + 13];
    const float* c2_bq    = (const float*)d_in[wbase + 14];
    const float* c2_Wv    = (const float*)d_in[wbase + 15];
    const float* c2_bv    = (const float*)d_in[wbase + 16];
    const float* c2_a_rel = (const float*)d_in[wbase + 17];
    const float* c2_m_rel = (const float*)d_in[wbase + 18];
    const float* c2_p_rel = (const float*)d_in[wbase + 19];
    const float* c2_Wa    = (const float*)d_in[wbase + 20];
    const float* c2_ba    = (const float*)d_in[wbase + 21];
    const float* c2_skip  = (const float*)d_in[wbase + 22];
    const float* Wc       = (const float*)d_in[wbase + 23];
    const float* bc       = (const float*)d_in[wbase + 24];

    int N_TX = in_sizes[0] / 128;
    int N_M  = in_sizes[1] / 128;
    int E0 = in_sizes[ebase + 1];
    int E1 = in_sizes[ebase + 3];

    void* p;
    float *q_tx, *q_m, *agg_tx, *agg_m, *h_tx, *h_m;
    float *WA1, *bA1, *WB1, *bB1, *WA2, *bA2, *WB2, *bB2;
    __half *kv_tx, *kv_m;
    int *rowptr0, *rowptr1, *cursor0, *cursor1, *srcs0, *srcs1;
    cudaGetSymbolAddress(&p, g_q_tx);    q_tx    = (float*)p;
    cudaGetSymbolAddress(&p, g_q_m);     q_m     = (float*)p;
    cudaGetSymbolAddress(&p, g_kv_tx);   kv_tx   = (__half*)p;
    cudaGetSymbolAddress(&p, g_kv_m);    kv_m    = (__half*)p;
    cudaGetSymbolAddress(&p, g_agg_tx);  agg_tx  = (float*)p;
    cudaGetSymbolAddress(&p, g_agg_m);   agg_m   = (float*)p;
    cudaGetSymbolAddress(&p, g_h_tx);    h_tx    = (float*)p;
    cudaGetSymbolAddress(&p, g_h_m);     h_m     = (float*)p;
    cudaGetSymbolAddress(&p, g_WA1);     WA1     = (float*)p;
    cudaGetSymbolAddress(&p, g_bA1);     bA1     = (float*)p;
    cudaGetSymbolAddress(&p, g_WB1);     WB1     = (float*)p;
    cudaGetSymbolAddress(&p, g_bB1);     bB1     = (float*)p;
    cudaGetSymbolAddress(&p, g_WA2);     WA2     = (float*)p;
    cudaGetSymbolAddress(&p, g_bA2);     bA2     = (float*)p;
    cudaGetSymbolAddress(&p, g_WB2);     WB2     = (float*)p;
    cudaGetSymbolAddress(&p, g_bB2);     bB2     = (float*)p;
    cudaGetSymbolAddress(&p, g_rowptr0); rowptr0 = (int*)p;
    cudaGetSymbolAddress(&p, g_rowptr1); rowptr1 = (int*)p;
    cudaGetSymbolAddress(&p, g_cursor0); cursor0 = (int*)p;
    cudaGetSymbolAddress(&p, g_cursor1); cursor1 = (int*)p;
    cudaGetSymbolAddress(&p, g_srcs0);   srcs0   = (int*)p;
    cudaGetSymbolAddress(&p, g_srcs1);   srcs1   = (int*)p;

    int gbTX = (N_TX + 127) / 128;
    int gbM  = (N_M + 127) / 128;

    // ---- 1-4: CSR build (merged) ----
    zero_both_kernel<<<(N_M + N_TX + 255) / 256, 256>>>(cursor0, N_M, cursor1, N_TX);
    hist_both_kernel<<<(E0 + E1 + 255) / 256, 256>>>(tm_dst, E0, cursor0, mt_dst, E1, cursor1);
    scan_both_kernel<<<2, 1024>>>(cursor0, rowptr0, N_M, cursor1, rowptr1, N_TX);
    scatter_both_kernel<<<(E0 + E1 + 255) / 256, 256>>>(
        tm_src, tm_dst, E0, cursor0, srcs0, mt_src, mt_dst, E1, cursor1, srcs1);

    // ---- 5: all effective weights ----
    eff_all_kernel<<<dim3(97, 4), 256>>>(
        c1_Wq, c1_bq, c1_Wk, c1_bk, c1_Wv, c1_bv, c1_a_rel, c1_m_rel,
        c2_Wq, c2_bq, c2_Wk, c2_bk, c2_Wv, c2_bv, c2_a_rel, c2_m_rel,
        WA1, bA1, WB1, bB1, WA2, bA2, WB2, bB2);

    // ---- 6: layer-1 QKV GEMM, tx + m merged, NCOLS=96 (2 col-blocks) ----
    {
        GemmJob j0 = { x_tx, WA1, bA1, nullptr, q_tx, kv_tx, N_TX, 192, 0, 64, 2 };
        GemmJob j1 = { x_m,  WB1, bB1, nullptr, q_m,  kv_m,  N_M,  192, 0, 64, 2 };
        int nb0 = gbTX * 2;
        mma_gemm_kernel<0, 0, 96><<<nb0 + gbM * 2, 256>>>(j0, j1, nb0, 128, nullptr);
    }

    // ---- 7: layer-1 attention, both directions merged ----
    {
        AttnSet s0 = { kv_tx, q_m,  rowptr0, srcs0, c1_p_rel,     agg_m,  N_M };
        AttnSet s1 = { kv_m,  q_tx, rowptr1, srcs1, c1_p_rel + 4, agg_tx, N_TX };
        attn_kernel<<<(N_M + N_TX + 7) / 8, 256>>>(s0, s1);
    }

    // ---- 8: layer-1 epilogue, tx + m merged: h = relu(gelu(agg) @ Wa + ba) ----
    {
        GemmJob j0 = { agg_tx, c1_Wa,        c1_ba,      nullptr, h_tx, nullptr, N_TX, 64, 0, 64, 1 };
        GemmJob j1 = { agg_m,  c1_Wa + 4096, c1_ba + 64, nullptr, h_m,  nullptr, N_M,  64, 0, 64, 1 };
        mma_gemm_kernel<1, 1, 64><<<gbTX + gbM, 256>>>(j0, j1, gbTX, 64, nullptr);
    }

    // ---- 9: layer-2 projections merged: tx Q (cols 0..63) + m KV (cols 64..191) ----
    {
        GemmJob j0 = { h_tx, WA2, bA2, nullptr, q_tx,    nullptr, N_TX, 192, 0,  64, 1 };
        GemmJob j1 = { h_m,  WB2, bB2, nullptr, nullptr, kv_m,    N_M,  192, 64, 0,  2 };
        mma_gemm_kernel<0, 0, 64><<<gbTX + gbM * 2, 256>>>(j0, j1, gbTX, 64, nullptr);
    }

    // ---- 10: layer-2 attention (tx dst only) ----
    {
        AttnSet s1 = { kv_m, q_tx, rowptr1, srcs1, c2_p_rel + 4, agg_tx, N_TX };
        AttnSet s0 = s1; s0.n = 0;
        attn_kernel<<<(N_TX + 7) / 8, 256>>>(s0, s1);
    }

    // ---- 11: layer-2 epilogue with skip mix, in place on h_tx ----
    {
        GemmJob j0 = { agg_tx, c2_Wa, c2_ba, h_tx, h_tx, nullptr, N_TX, 64, 0, 64, 1 };
        mma_gemm_kernel<2, 1, 64><<<gbTX, 256>>>(j0, j0, gbTX, 64, c2_skip);
    }

    // ---- 12: logits ----
    final_kernel<<<(N_TX + 7) / 8, 256>>>(h_tx, Wc, bc, (float*)d_out, N_TX);
}